// round 13
// baseline (speedup 1.0000x reference)
#include <cuda_runtime.h>
#include <cuda_bf16.h>
#include <cstdint>
#include <cstddef>

typedef unsigned long long ull;

// Problem constants
#define BB 64
#define SS 1024
#define II 256
#define HH 256

// Scratch: X gate pre-activations [S][B][4*H] fp32, biases included. 256MB.
__device__ float g_X[(size_t)SS * BB * 4 * HH];
// Split-bf16 planes of A (inputs, [B*S][I]) and W (4 gates concat, [1024][256]).
__device__ __nv_bfloat16 g_A_hi[(size_t)BB * SS * II];
__device__ __nv_bfloat16 g_A_lo[(size_t)BB * SS * II];
__device__ __nv_bfloat16 g_W_hi[4 * HH * II];
__device__ __nv_bfloat16 g_W_lo[4 * HH * II];

// ---------------- f32x2 helpers (PTX-only dual-FMA path) ----------------
__device__ __forceinline__ ull pk2(float a, float b) {
    ull r; asm("mov.b64 %0, {%1, %2};" : "=l"(r) : "f"(a), "f"(b)); return r;
}
__device__ __forceinline__ void upk2(ull v, float& a, float& b) {
    asm("mov.b64 {%0, %1}, %2;" : "=f"(a), "=f"(b) : "l"(v));
}
__device__ __forceinline__ ull fma2(ull a, ull b, ull c) {
    ull d; asm("fma.rn.f32x2 %0, %1, %2, %3;" : "=l"(d) : "l"(a), "l"(b), "l"(c)); return d;
}

// Accurate fast activations (ex2/rcp approx: ~2^-22 rel err, >> 1e-3 budget)
__device__ __forceinline__ float fast_sigmoid(float x) {
    float e; asm("ex2.approx.f32 %0, %1;" : "=f"(e) : "f"(-x * 1.4426950408889634f));
    float r; asm("rcp.approx.f32 %0, %1;" : "=f"(r) : "f"(1.0f + e));
    return r;
}
__device__ __forceinline__ float fast_tanh(float x) {
    x = fminf(15.0f, fmaxf(-15.0f, x));
    float e; asm("ex2.approx.f32 %0, %1;" : "=f"(e) : "f"(x * 2.8853900817779268f)); // e^{2x}
    float r; asm("rcp.approx.f32 %0, %1;" : "=f"(r) : "f"(e + 1.0f));
    return fmaf(-2.0f, r, 1.0f);
}

// ---------------- warp-level bf16 HMMA -----------------------------------
__device__ __forceinline__ void mma_bf16(float* d, const uint32_t* a,
                                         const uint32_t* b) {
    asm volatile(
        "mma.sync.aligned.m16n8k16.row.col.f32.bf16.bf16.f32 "
        "{%0,%1,%2,%3}, {%4,%5,%6,%7}, {%8,%9}, {%0,%1,%2,%3};"
        : "+f"(d[0]), "+f"(d[1]), "+f"(d[2]), "+f"(d[3])
        : "r"(a[0]), "r"(a[1]), "r"(a[2]), "r"(a[3]), "r"(b[0]), "r"(b[1]));
}

// =====================================================================
// Split-bf16 conversion:  x -> (hi, lo) with x = hi + lo + O(2^-18 x)
// =====================================================================
__global__ void cvt_split(const float* __restrict__ src,
                          __nv_bfloat16* __restrict__ hi,
                          __nv_bfloat16* __restrict__ lo, int n4)
{
    int i = blockIdx.x * blockDim.x + threadIdx.x;
    int stride = gridDim.x * blockDim.x;
    for (; i < n4; i += stride) {
        float4 v = ((const float4*)src)[i];
        float f[4] = {v.x, v.y, v.z, v.w};
        unsigned short hb[4], lb[4];
#pragma unroll
        for (int c = 0; c < 4; c++) {
            __nv_bfloat16 h = __float2bfloat16(f[c]);
            float hf = __bfloat162float(h);
            __nv_bfloat16 l = __float2bfloat16(f[c] - hf);
            hb[c] = __bfloat16_as_ushort(h);
            lb[c] = __bfloat16_as_ushort(l);
        }
        ((ushort4*)hi)[i] = make_ushort4(hb[0], hb[1], hb[2], hb[3]);
        ((ushort4*)lo)[i] = make_ushort4(lb[0], lb[1], lb[2], lb[3]);
    }
}

// =====================================================================
// Phase 1 (tensor pipe, warp HMMA): X = inputs . W^T + bias, 3-term
// bf16 split. UNCHANGED (passed, ~300us).
// =====================================================================
#define XT_ROWB 80
#define XT_TILE (128 * XT_ROWB)
#define XT_AHI 0
#define XT_ALO (1 * XT_TILE)
#define XT_BHI (2 * XT_TILE)
#define XT_BLO (3 * XT_TILE)
#define XT_BIAS (4 * XT_TILE)
#define XT_SMEM (XT_BIAS + 512)

__global__ void __launch_bounds__(256, 2) lstm_xproj_tc(
    const float* __restrict__ bii, const float* __restrict__ bif_,
    const float* __restrict__ big_, const float* __restrict__ bio,
    const float* __restrict__ bhi, const float* __restrict__ bhf,
    const float* __restrict__ bhg, const float* __restrict__ bho)
{
    __shared__ char smc[XT_SMEM];
    const int tid = threadIdx.x;
    const int lane = tid & 31, wid = tid >> 5;
    const int warpM = wid >> 2, warpN = wid & 3;
    const int gID = lane >> 2, tig = lane & 3;
    const int n0 = blockIdx.x << 7;
    const int m0 = blockIdx.y << 7;

    if (tid < 128) {
        int n = n0 + tid;
        int g = n >> 8, u = n & 255;
        const float* bi = (g == 0) ? bii : (g == 1) ? bif_ : (g == 2) ? big_ : bio;
        const float* bh = (g == 0) ? bhi : (g == 1) ? bhf : (g == 2) ? bhg : bho;
        ((float*)(smc + XT_BIAS))[tid] = bi[u] + bh[u];
    }

    float d[4][4][4];
#pragma unroll
    for (int mf = 0; mf < 4; mf++)
#pragma unroll
        for (int nf = 0; nf < 4; nf++)
#pragma unroll
            for (int c = 0; c < 4; c++) d[mf][nf][c] = 0.0f;

    const int aRow = warpM * 64 + gID;
    const int bRow = warpN * 32 + gID;

#pragma unroll 1
    for (int ch = 0; ch < 8; ch++) {
        const int k0 = ch << 5;
#pragma unroll
        for (int part = 0; part < 8; part++) {
            const int tile = part >> 1;
            int idx = part * 256 + tid;
            int r = (idx >> 2) & 127;
            int k8 = idx & 3;
            const __nv_bfloat16* src;
            if (tile == 0)      src = g_A_hi + (((size_t)(m0 + r)) << 8) + k0 + (k8 << 3);
            else if (tile == 1) src = g_A_lo + (((size_t)(m0 + r)) << 8) + k0 + (k8 << 3);
            else if (tile == 2) src = g_W_hi + (((size_t)(n0 + r)) << 8) + k0 + (k8 << 3);
            else                src = g_W_lo + (((size_t)(n0 + r)) << 8) + k0 + (k8 << 3);
            uint4 v = *(const uint4*)src;
            *(uint4*)(smc + tile * XT_TILE + r * XT_ROWB + (k8 << 4)) = v;
        }
        __syncthreads();

#pragma unroll
        for (int ks = 0; ks < 2; ks++) {
            const int kb2 = (ks * 16 + tig * 2) * 2;
            uint32_t a[4][4], bh2[4][2], bl2[4][2];
#pragma unroll
            for (int mf = 0; mf < 4; mf++) {
                const char* base = smc + XT_AHI + (aRow + mf * 16) * XT_ROWB + kb2;
                a[mf][0] = *(const uint32_t*)(base);
                a[mf][1] = *(const uint32_t*)(base + 8 * XT_ROWB);
                a[mf][2] = *(const uint32_t*)(base + 16);
                a[mf][3] = *(const uint32_t*)(base + 8 * XT_ROWB + 16);
            }
#pragma unroll
            for (int nf = 0; nf < 4; nf++) {
                const char* bh_b = smc + XT_BHI + (bRow + nf * 8) * XT_ROWB + kb2;
                bh2[nf][0] = *(const uint32_t*)(bh_b);
                bh2[nf][1] = *(const uint32_t*)(bh_b + 16);
                const char* bl_b = smc + XT_BLO + (bRow + nf * 8) * XT_ROWB + kb2;
                bl2[nf][0] = *(const uint32_t*)(bl_b);
                bl2[nf][1] = *(const uint32_t*)(bl_b + 16);
            }
#pragma unroll
            for (int mf = 0; mf < 4; mf++)
#pragma unroll
                for (int nf = 0; nf < 4; nf++) {
                    mma_bf16(d[mf][nf], a[mf], bh2[nf]);
                    mma_bf16(d[mf][nf], a[mf], bl2[nf]);
                }
#pragma unroll
            for (int mf = 0; mf < 4; mf++) {
                const char* base = smc + XT_ALO + (aRow + mf * 16) * XT_ROWB + kb2;
                a[mf][0] = *(const uint32_t*)(base);
                a[mf][1] = *(const uint32_t*)(base + 8 * XT_ROWB);
                a[mf][2] = *(const uint32_t*)(base + 16);
                a[mf][3] = *(const uint32_t*)(base + 8 * XT_ROWB + 16);
            }
#pragma unroll
            for (int mf = 0; mf < 4; mf++)
#pragma unroll
                for (int nf = 0; nf < 4; nf++)
                    mma_bf16(d[mf][nf], a[mf], bh2[nf]);
        }
        __syncthreads();
    }

    const float* biasS = (const float*)(smc + XT_BIAS);
#pragma unroll
    for (int mf = 0; mf < 4; mf++)
#pragma unroll
        for (int nf = 0; nf < 4; nf++)
#pragma unroll
            for (int r8 = 0; r8 < 2; r8++) {
                int m = m0 + warpM * 64 + mf * 16 + gID + r8 * 8;
                int nl = warpN * 32 + nf * 8 + tig * 2;
                int b_ = m >> 10, s = m & 1023;
                float2 v;
                v.x = d[mf][nf][r8 * 2 + 0] + biasS[nl];
                v.y = d[mf][nf][r8 * 2 + 1] + biasS[nl + 1];
                *(float2*)&g_X[(size_t)((s << 6) + b_) * 1024 + n0 + nl] = v;
            }
}

// =====================================================================
// Phase 2: scan with TWO-GROUP SOFTWARE PIPELINE. Each cluster's 4
// batches split into group A (b0+0,1) and group B (b0+2,3) — independent
// recurrences. While A's h-exchange is in flight, the CTA computes B,
// and vice versa: exchange latency hides under the other group's GEMM.
// Iteration t: waitA -> S1 -> [tailB(t-1) || GEMM_A(t)] -> waitB ->
// S2 -> [tailA(t) || GEMM_B(t)]. Tail warps: A = warps 0-1, B = 8-9.
// Waiter = warp 15. Per-group copies: 7 x 256B, expect_tx 1792.
// =====================================================================
// SMEM float offsets:
#define HSA 0        // HsmA [2][8rblk][2b][32u] = 1024 floats
#define HSB 1024     // HsmB same
#define RDA 2048     // RedA [2b][8ks][128rows] = 2048
#define RDB 4096     // RedB
#define STA 6144     // StgA [2][64]
#define STB 6272     // StgB [2][64]
#define SM_FLOATS 6400

__global__ void __cluster_dims__(8, 1, 1) __launch_bounds__(512, 1)
lstm_scan(const float* __restrict__ h0, const float* __restrict__ c0,
          const float* __restrict__ whi, const float* __restrict__ whf,
          const float* __restrict__ whg, const float* __restrict__ who,
          float* __restrict__ out, int out_size)
{
    __shared__ float sm[SM_FLOATS];
    __shared__ __align__(16) ull mbars[4];

    const int tid = threadIdx.x;
    unsigned rank; asm("mov.u32 %0, %%cluster_ctarank;" : "=r"(rank));
    const int b0 = (blockIdx.x >> 3) * 4;

    // GEMM roles: ks = 32-float k-slice (warp-pair uniform), j2 = row pair
    const int ks = tid >> 6;                  // 0..7
    const int j2 = tid & 63;
    const int r0 = j2 << 1;                   // rows r0, r0+1 (0..127)
    const int g  = r0 >> 5, uu0 = r0 & 31;

    const float* W = (g == 0) ? whi : (g == 1) ? whf : (g == 2) ? whg : who;

    // weights: 2 rows x 32 floats
    ull w2[32];
#pragma unroll
    for (int r = 0; r < 2; r++) {
        const ulonglong2* wp = (const ulonglong2*)(
            W + (size_t)(((int)rank << 5) + uu0 + r) * 256 + (ks << 5));
#pragma unroll
        for (int c4 = 0; c4 < 8; c4++) {
            ulonglong2 wq = wp[c4];
            w2[r * 16 + 2 * c4]     = wq.x;
            w2[r * 16 + 2 * c4 + 1] = wq.y;
        }
    }

    // h0 into buffer 0 of both groups: [rblk][b][u]
    if (tid < 512) {
        int rblk = tid >> 6, b = (tid >> 5) & 1, u = tid & 31;
        sm[HSA + tid] = h0[(size_t)(b0 + b) * 256 + (rblk << 5) + u];
        sm[HSB + tid] = h0[(size_t)(b0 + 2 + b) * 256 + (rblk << 5) + u];
    }

    // tail roles
    const bool isTA = (tid < 64);             // warps 0-1
    const bool isTB = (tid >= 256 && tid < 320); // warps 8-9
    const int tb = tid - 256;
    const int cuA = tid & 31, cbA = (tid >> 5) & 1;
    const int cuB = tb & 31,  cbB = (tb >> 5) & 1;
    const int ugA = ((int)rank << 5) + cuA;
    const int ugB = ((int)rank << 5) + cuB;
    float cA = 0.0f, cB = 0.0f;
    if (isTA) cA = c0[(size_t)(b0 + cbA) * 256 + ugA];
    if (isTB) cB = c0[(size_t)(b0 + 2 + cbB) * 256 + ugB];

    unsigned smem_u32, mbar_base;
    asm("{ .reg .u64 t; cvta.to.shared.u64 t, %1; cvt.u32.u64 %0, t; }"
        : "=r"(smem_u32) : "l"(sm));
    asm("{ .reg .u64 t; cvta.to.shared.u64 t, %1; cvt.u32.u64 %0, t; }"
        : "=r"(mbar_base) : "l"(mbars));
    const unsigned mbarA0 = mbar_base,      mbarA1 = mbar_base + 8;
    const unsigned mbarB0 = mbar_base + 16, mbarB1 = mbar_base + 24;

    // copy-lane peer (A: lanes 0..6 of warp0; B: lanes 0..6 of warp8)
    int cl = (tid < 7) ? tid : ((tid >= 256 && tid < 263) ? tid - 256 : -1);
    const int peer = (cl >= 0) ? ((cl >= (int)rank) ? cl + 1 : cl) : 0;

    if (tid == 0) {
        asm volatile("mbarrier.init.shared.b64 [%0], 1;" :: "r"(mbarA0) : "memory");
        asm volatile("mbarrier.init.shared.b64 [%0], 1;" :: "r"(mbarA1) : "memory");
        asm volatile("mbarrier.init.shared.b64 [%0], 1;" :: "r"(mbarB0) : "memory");
        asm volatile("mbarrier.init.shared.b64 [%0], 1;" :: "r"(mbarB1) : "memory");
    }
    __syncthreads();
    asm volatile("barrier.cluster.arrive.aligned;" ::: "memory");
    asm volatile("barrier.cluster.wait.aligned;" ::: "memory");

    unsigned phA0 = 0, phA1 = 0, phB0 = 0, phB1 = 0;
    float xA0 = 0.f, xA1 = 0.f, xA2 = 0.f, xA3 = 0.f;
    float xB0 = 0.f, xB1 = 0.f, xB2 = 0.f, xB3 = 0.f;

    for (int t = 0; t < SS; t++) {
        const int p = t & 1;

        // ---- xA prefetch for step t (consumed at tailA(t) this iteration)
        if (isTA) {
            const float* xp = g_X + (size_t)t * 65536
                            + (size_t)(b0 + cbA) * 1024 + ugA;
            xA0 = xp[0]; xA1 = xp[256]; xA2 = xp[512]; xA3 = xp[768];
        }

        // ---- waitA(t): warp 15 polls; S1 releases
        if (t > 0) {
            if (tid >= 480) {
                const unsigned wb  = p ? mbarA1 : mbarA0;
                const unsigned phw = p ? phA1 : phA0;
                if (tid == 480)
                    asm volatile("mbarrier.arrive.expect_tx.shared.b64 _, [%0], %1;"
                                 :: "r"(wb), "r"(1792u) : "memory");
                asm volatile("{\n\t.reg .pred P1;\n\t"
                    "LWA_%=:\n\t"
                    "mbarrier.try_wait.parity.acquire.cta.shared::cta.b64 P1, [%0], %1, 0x989680;\n\t"
                    "@P1 bra.uni LDA_%=;\n\t"
                    "bra.uni LWA_%=;\n\t"
                    "LDA_%=:\n\t}"
                    :: "r"(wb), "r"(phw) : "memory");
            }
            if (p) phA1 ^= 1; else phA0 ^= 1;
        }
        __syncthreads();   // S1: HsmA[p] ready; RedB(t-1) visible

        // ---- tailB(t-1) on warps 8-9 (overlaps GEMM_A on other warps)
        if (isTB && t > 0) {
            const int tm1 = t - 1;
            const float* rb = sm + RDB + (cbB << 10) + cuB + (g == 0 ? 0 : 0); // base
            float pi = 0.f, pf = 0.f, pg = 0.f, po = 0.f;
#pragma unroll
            for (int kk = 0; kk < 8; kk++) {
                const float* rk = sm + RDB + (cbB << 10) + (kk << 7) + cuB;
                pi += rk[0]; pf += rk[32]; pg += rk[64]; po += rk[96];
            }
            (void)rb;
            pi += xB0; pf += xB1; pg += xB2; po += xB3;
            float gi = fast_sigmoid(pi);
            float gf = fast_sigmoid(pf);
            float gg = fast_tanh(pg);
            float go = fast_sigmoid(po);
            cB = gf * cB + gi * gg;
            float h = go * fast_tanh(cB);

            // stage (parity 1-p = tm1&1) + own block into HsmB[p]
            sm[STB + ((1 - p) << 6) + (cbB << 5) + cuB] = h;
            sm[HSB + (p << 9) + ((int)rank << 6) + (cbB << 5) + cuB] = h;
            asm volatile("bar.sync 2, 64;" ::: "memory");

            if (tb < 7) {   // tm1 <= SS-2 always here: copies always sent
                asm volatile("fence.proxy.async.shared::cta;" ::: "memory");
                unsigned dstl = smem_u32 + 4096u + ((unsigned)p << 11)
                              + ((unsigned)rank << 8);
                unsigned mbl  = p ? mbarB1 : mbarB0;
                unsigned srcl = smem_u32 + (STB << 2) + ((unsigned)(1 - p) << 8);
                unsigned rdst, rmb;
                asm volatile("mapa.shared::cluster.u32 %0, %1, %2;"
                             : "=r"(rdst) : "r"(dstl), "r"(peer));
                asm volatile("mapa.shared::cluster.u32 %0, %1, %2;"
                             : "=r"(rmb) : "r"(mbl), "r"(peer));
                asm volatile(
                    "cp.async.bulk.shared::cluster.shared::cta."
                    "mbarrier::complete_tx::bytes [%0], [%1], 256, [%2];"
                    :: "r"(rdst), "r"(srcl), "r"(rmb) : "memory");
            }

            float h_hi = __shfl_down_sync(0xffffffffu, h, 1);
            if ((cuB & 1) == 0) {
                *(float2*)&out[((size_t)(b0 + 2 + cbB) * 1024 + tm1) * 256 + ugB] =
                    make_float2(h, h_hi);
            }
        }

        // ---- xB prefetch for step t (consumed at tailB(t) next iteration)
        if (isTB) {
            const float* xp = g_X + (size_t)t * 65536
                            + (size_t)(b0 + 2 + cbB) * 1024 + ugB;
            xB0 = xp[0]; xB1 = xp[256]; xB2 = xp[512]; xB3 = xp[768];
        }

        // ---- GEMM_A(t): 2 rows x 2 batches x 32-k (broadcast LDS.128)
        {
            const float* hb = sm + HSA + (p << 9) + (ks << 6);
            ull a00 = 0, a01 = 0, a10 = 0, a11 = 0;
#pragma unroll
            for (int c = 0; c < 8; c++) {
                ulonglong2 hq0 = *(const ulonglong2*)(hb + 0 * 32 + (c << 2));
                ulonglong2 hq1 = *(const ulonglong2*)(hb + 1 * 32 + (c << 2));
                ull w0lo = w2[2*c], w0hi = w2[2*c+1];
                ull w1lo = w2[16 + 2*c], w1hi = w2[16 + 2*c+1];
                a00 = fma2(w0hi, hq0.y, fma2(w0lo, hq0.x, a00));
                a01 = fma2(w0hi, hq1.y, fma2(w0lo, hq1.x, a01));
                a10 = fma2(w1hi, hq0.y, fma2(w1lo, hq0.x, a10));
                a11 = fma2(w1hi, hq1.y, fma2(w1lo, hq1.x, a11));
            }
            float lo, hi, s00, s01, s10, s11;
            upk2(a00, lo, hi); s00 = lo + hi;
            upk2(a01, lo, hi); s01 = lo + hi;
            upk2(a10, lo, hi); s10 = lo + hi;
            upk2(a11, lo, hi); s11 = lo + hi;
            float* rp = sm + RDA + (ks << 7) + r0;
            *(float2*)(rp)        = make_float2(s00, s10);
            *(float2*)(rp + 1024) = make_float2(s01, s11);
        }

        // ---- waitB(t): warp 15 polls (after its GEMM_A share)
        if (t > 0) {
            if (tid >= 480) {
                const unsigned wb  = p ? mbarB1 : mbarB0;
                const unsigned phw = p ? phB1 : phB0;
                if (tid == 480)
                    asm volatile("mbarrier.arrive.expect_tx.shared.b64 _, [%0], %1;"
                                 :: "r"(wb), "r"(1792u) : "memory");
                asm volatile("{\n\t.reg .pred P1;\n\t"
                    "LWB_%=:\n\t"
                    "mbarrier.try_wait.parity.acquire.cta.shared::cta.b64 P1, [%0], %1, 0x989680;\n\t"
                    "@P1 bra.uni LDB_%=;\n\t"
                    "bra.uni LWB_%=;\n\t"
                    "LDB_%=:\n\t}"
                    :: "r"(wb), "r"(phw) : "memory");
            }
            if (p) phB1 ^= 1; else phB0 ^= 1;
        }
        __syncthreads();   // S2: RedA visible; HsmB[p] ready

        // ---- tailA(t) on warps 0-1 (overlaps GEMM_B on other warps)
        if (isTA) {
            float pi = 0.f, pf = 0.f, pg = 0.f, po = 0.f;
#pragma unroll
            for (int kk = 0; kk < 8; kk++) {
                const float* rk = sm + RDA + (cbA << 10) + (kk << 7) + cuA;
                pi += rk[0]; pf += rk[32]; pg += rk[64]; po += rk[96];
            }
            pi += xA0; pf += xA1; pg += xA2; po += xA3;
            float gi = fast_sigmoid(pi);
            float gf = fast_sigmoid(pf);
            float gg = fast_tanh(pg);
            float go = fast_sigmoid(po);
            cA = gf * cA + gi * gg;
            float h = go * fast_tanh(cA);

            sm[STA + (p << 6) + (cbA << 5) + cuA] = h;
            sm[HSA + ((1 - p) << 9) + ((int)rank << 6) + (cbA << 5) + cuA] = h;
            asm volatile("bar.sync 1, 64;" ::: "memory");

            if (tid < 7 && t < SS - 1) {
                asm volatile("fence.proxy.async.shared::cta;" ::: "memory");
                unsigned dstl = smem_u32 + (((unsigned)(1 - p)) << 11)
                              + ((unsigned)rank << 8);
                unsigned mbl  = p ? mbarA0 : mbarA1;
                unsigned srcl = smem_u32 + (STA << 2) + ((unsigned)p << 8);
                unsigned rdst, rmb;
                asm volatile("mapa.shared::cluster.u32 %0, %1, %2;"
                             : "=r"(rdst) : "r"(dstl), "r"(peer));
                asm volatile("mapa.shared::cluster.u32 %0, %1, %2;"
                             : "=r"(rmb) : "r"(mbl), "r"(peer));
                asm volatile(
                    "cp.async.bulk.shared::cluster.shared::cta."
                    "mbarrier::complete_tx::bytes [%0], [%1], 256, [%2];"
                    :: "r"(rdst), "r"(srcl), "r"(rmb) : "memory");
            }

            float h_hi = __shfl_down_sync(0xffffffffu, h, 1);
            if ((cuA & 1) == 0) {
                *(float2*)&out[((size_t)(b0 + cbA) * 1024 + t) * 256 + ugA] =
                    make_float2(h, h_hi);
            }
            if (t == SS - 1) {
                size_t basee = (size_t)BB * SS * HH;
                if (out_size >= (int)(basee + 2u * BB * HH)) {
                    out[basee + (size_t)(b0 + cbA) * 256 + ugA] = h;
                    out[basee + (size_t)BB * HH + (size_t)(b0 + cbA) * 256 + ugA] = cA;
                }
            }
        }

        // ---- GEMM_B(t)
        {
            const float* hb = sm + HSB + (p << 9) + (ks << 6);
            ull a00 = 0, a01 = 0, a10 = 0, a11 = 0;
#pragma unroll
            for (int c = 0; c < 8; c++) {
                ulonglong2 hq0 = *(const ulonglong2*)(hb + 0 * 32 + (c << 2));
                ulonglong2 hq1 = *(const ulonglong2*)(hb + 1 * 32 + (c << 2));
                ull w0lo = w2[2*c], w0hi = w2[2*c+1];
                ull w1lo = w2[16 + 2*c], w1hi = w2[16 + 2*c+1];
                a00 = fma2(w0hi, hq0.y, fma2(w0lo, hq0.x, a00));
                a01 = fma2(w0hi, hq1.y, fma2(w0lo, hq1.x, a01));
                a10 = fma2(w1hi, hq0.y, fma2(w1lo, hq0.x, a10));
                a11 = fma2(w1hi, hq1.y, fma2(w1lo, hq1.x, a11));
            }
            float lo, hi, s00, s01, s10, s11;
            upk2(a00, lo, hi); s00 = lo + hi;
            upk2(a01, lo, hi); s01 = lo + hi;
            upk2(a10, lo, hi); s10 = lo + hi;
            upk2(a11, lo, hi); s11 = lo + hi;
            float* rp = sm + RDB + (ks << 7) + r0;
            *(float2*)(rp)        = make_float2(s00, s10);
            *(float2*)(rp + 1024) = make_float2(s01, s11);
        }
    }

    // ---- final tailB(SS-1)
    __syncthreads();
    if (isTB) {
        float pi = 0.f, pf = 0.f, pg = 0.f, po = 0.f;
#pragma unroll
        for (int kk = 0; kk < 8; kk++) {
            const float* rk = sm + RDB + (cbB << 10) + (kk << 7) + cuB;
            pi += rk[0]; pf += rk[32]; pg += rk[64]; po += rk[96];
        }
        pi += xB0; pf += xB1; pg += xB2; po += xB3;
        float gi = fast_sigmoid(pi);
        float gf = fast_sigmoid(pf);
        float gg = fast_tanh(pg);
        float go = fast_sigmoid(po);
        cB = gf * cB + gi * gg;
        float h = go * fast_tanh(cB);

        float h_hi = __shfl_down_sync(0xffffffffu, h, 1);
        if ((cuB & 1) == 0) {
            *(float2*)&out[((size_t)(b0 + 2 + cbB) * 1024 + (SS - 1)) * 256 + ugB] =
                make_float2(h, h_hi);
        }
        size_t basee = (size_t)BB * SS * HH;
        if (out_size >= (int)(basee + 2u * BB * HH)) {
            out[basee + (size_t)(b0 + 2 + cbB) * 256 + ugB] = h;
            out[basee + (size_t)BB * HH + (size_t)(b0 + 2 + cbB) * 256 + ugB] = cB;
        }
    }
}

// =====================================================================
extern "C" void kernel_launch(void* const* d_in, const int* in_sizes, int n_in,
                              void* d_out, int out_size)
{
    (void)in_sizes; (void)n_in;
    const float* inputs = (const float*)d_in[0];
    const float* h0     = (const float*)d_in[1];
    const float* c0     = (const float*)d_in[2];
    const float* w_ii   = (const float*)d_in[3];
    const float* w_if   = (const float*)d_in[4];
    const float* w_ig   = (const float*)d_in[5];
    const float* w_io   = (const float*)d_in[6];
    const float* b_ii   = (const float*)d_in[7];
    const float* b_if   = (const float*)d_in[8];
    const float* b_ig   = (const float*)d_in[9];
    const float* b_io   = (const float*)d_in[10];
    const float* w_hi   = (const float*)d_in[11];
    const float* w_hf   = (const float*)d_in[12];
    const float* w_hg   = (const float*)d_in[13];
    const float* w_ho   = (const float*)d_in[14];
    const float* b_hi   = (const float*)d_in[15];
    const float* b_hf   = (const float*)d_in[16];
    const float* b_hg   = (const float*)d_in[17];
    const float* b_ho   = (const float*)d_in[18];
    float* out = (float*)d_out;

    __nv_bfloat16 *ahi, *alo, *whi_p, *wlo_p;
    cudaGetSymbolAddress((void**)&ahi,   g_A_hi);
    cudaGetSymbolAddress((void**)&alo,   g_A_lo);
    cudaGetSymbolAddress((void**)&whi_p, g_W_hi);
    cudaGetSymbolAddress((void**)&wlo_p, g_W_lo);

    cvt_split<<<2048, 256>>>(inputs, ahi, alo, (BB * SS * II) / 4);
    cvt_split<<<64, 256>>>(w_ii, whi_p + 0 * 65536, wlo_p + 0 * 65536, 65536 / 4);
    cvt_split<<<64, 256>>>(w_if, whi_p + 1 * 65536, wlo_p + 1 * 65536, 65536 / 4);
    cvt_split<<<64, 256>>>(w_ig, whi_p + 2 * 65536, wlo_p + 2 * 65536, 65536 / 4);
    cvt_split<<<64, 256>>>(w_io, whi_p + 3 * 65536, wlo_p + 3 * 65536, 65536 / 4);

    lstm_xproj_tc<<<dim3(8, 512), 256>>>(
        b_ii, b_if, b_ig, b_io, b_hi, b_hf, b_hg, b_ho);

    lstm_scan<<<128, 512>>>(
        h0, c0, w_hi, w_hf, w_hg, w_ho, out, out_size);
}

// round 14
// speedup vs baseline: 1.2601x; 1.2601x over previous
#include <cuda_runtime.h>
#include <cuda_bf16.h>
#include <cstdint>
#include <cstddef>

typedef unsigned long long ull;

// Problem constants
#define BB 64
#define SS 1024
#define II 256
#define HH 256

// Scratch: X gate pre-activations [S][B][4*H] fp32, biases included. 256MB.
__device__ float g_X[(size_t)SS * BB * 4 * HH];
// Split-bf16 planes of A (inputs, [B*S][I]) and W (4 gates concat, [1024][256]).
__device__ __nv_bfloat16 g_A_hi[(size_t)BB * SS * II];
__device__ __nv_bfloat16 g_A_lo[(size_t)BB * SS * II];
__device__ __nv_bfloat16 g_W_hi[4 * HH * II];
__device__ __nv_bfloat16 g_W_lo[4 * HH * II];

// ---------------- f32x2 helpers (PTX-only dual-FMA path) ----------------
__device__ __forceinline__ ull pk2(float a, float b) {
    ull r; asm("mov.b64 %0, {%1, %2};" : "=l"(r) : "f"(a), "f"(b)); return r;
}
__device__ __forceinline__ void upk2(ull v, float& a, float& b) {
    asm("mov.b64 {%0, %1}, %2;" : "=f"(a), "=f"(b) : "l"(v));
}
__device__ __forceinline__ ull fma2(ull a, ull b, ull c) {
    ull d; asm("fma.rn.f32x2 %0, %1, %2, %3;" : "=l"(d) : "l"(a), "l"(b), "l"(c)); return d;
}

// Accurate fast activations (ex2/rcp approx: ~2^-22 rel err, >> 1e-3 budget)
__device__ __forceinline__ float fast_sigmoid(float x) {
    float e; asm("ex2.approx.f32 %0, %1;" : "=f"(e) : "f"(-x * 1.4426950408889634f));
    float r; asm("rcp.approx.f32 %0, %1;" : "=f"(r) : "f"(1.0f + e));
    return r;
}
__device__ __forceinline__ float fast_tanh(float x) {
    x = fminf(15.0f, fmaxf(-15.0f, x));
    float e; asm("ex2.approx.f32 %0, %1;" : "=f"(e) : "f"(x * 2.8853900817779268f)); // e^{2x}
    float r; asm("rcp.approx.f32 %0, %1;" : "=f"(r) : "f"(e + 1.0f));
    return fmaf(-2.0f, r, 1.0f);
}

// ---------------- warp-level bf16 HMMA -----------------------------------
__device__ __forceinline__ void mma_bf16(float* d, const uint32_t* a,
                                         const uint32_t* b) {
    asm volatile(
        "mma.sync.aligned.m16n8k16.row.col.f32.bf16.bf16.f32 "
        "{%0,%1,%2,%3}, {%4,%5,%6,%7}, {%8,%9}, {%0,%1,%2,%3};"
        : "+f"(d[0]), "+f"(d[1]), "+f"(d[2]), "+f"(d[3])
        : "r"(a[0]), "r"(a[1]), "r"(a[2]), "r"(a[3]), "r"(b[0]), "r"(b[1]));
}

// =====================================================================
// Split-bf16 conversion:  x -> (hi, lo) with x = hi + lo + O(2^-18 x)
// =====================================================================
__global__ void cvt_split(const float* __restrict__ src,
                          __nv_bfloat16* __restrict__ hi,
                          __nv_bfloat16* __restrict__ lo, int n4)
{
    int i = blockIdx.x * blockDim.x + threadIdx.x;
    int stride = gridDim.x * blockDim.x;
    for (; i < n4; i += stride) {
        float4 v = ((const float4*)src)[i];
        float f[4] = {v.x, v.y, v.z, v.w};
        unsigned short hb[4], lb[4];
#pragma unroll
        for (int c = 0; c < 4; c++) {
            __nv_bfloat16 h = __float2bfloat16(f[c]);
            float hf = __bfloat162float(h);
            __nv_bfloat16 l = __float2bfloat16(f[c] - hf);
            hb[c] = __bfloat16_as_ushort(h);
            lb[c] = __bfloat16_as_ushort(l);
        }
        ((ushort4*)hi)[i] = make_ushort4(hb[0], hb[1], hb[2], hb[3]);
        ((ushort4*)lo)[i] = make_ushort4(lb[0], lb[1], lb[2], lb[3]);
    }
}

// =====================================================================
// Phase 1 (tensor pipe, warp HMMA): X = inputs . W^T + bias, 3-term
// bf16 split. UNCHANGED (passed, ~300us).
// =====================================================================
#define XT_ROWB 80
#define XT_TILE (128 * XT_ROWB)
#define XT_AHI 0
#define XT_ALO (1 * XT_TILE)
#define XT_BHI (2 * XT_TILE)
#define XT_BLO (3 * XT_TILE)
#define XT_BIAS (4 * XT_TILE)
#define XT_SMEM (XT_BIAS + 512)

__global__ void __launch_bounds__(256, 2) lstm_xproj_tc(
    const float* __restrict__ bii, const float* __restrict__ bif_,
    const float* __restrict__ big_, const float* __restrict__ bio,
    const float* __restrict__ bhi, const float* __restrict__ bhf,
    const float* __restrict__ bhg, const float* __restrict__ bho)
{
    __shared__ char smc[XT_SMEM];
    const int tid = threadIdx.x;
    const int lane = tid & 31, wid = tid >> 5;
    const int warpM = wid >> 2, warpN = wid & 3;
    const int gID = lane >> 2, tig = lane & 3;
    const int n0 = blockIdx.x << 7;
    const int m0 = blockIdx.y << 7;

    if (tid < 128) {
        int n = n0 + tid;
        int g = n >> 8, u = n & 255;
        const float* bi = (g == 0) ? bii : (g == 1) ? bif_ : (g == 2) ? big_ : bio;
        const float* bh = (g == 0) ? bhi : (g == 1) ? bhf : (g == 2) ? bhg : bho;
        ((float*)(smc + XT_BIAS))[tid] = bi[u] + bh[u];
    }

    float d[4][4][4];
#pragma unroll
    for (int mf = 0; mf < 4; mf++)
#pragma unroll
        for (int nf = 0; nf < 4; nf++)
#pragma unroll
            for (int c = 0; c < 4; c++) d[mf][nf][c] = 0.0f;

    const int aRow = warpM * 64 + gID;
    const int bRow = warpN * 32 + gID;

#pragma unroll 1
    for (int ch = 0; ch < 8; ch++) {
        const int k0 = ch << 5;
#pragma unroll
        for (int part = 0; part < 8; part++) {
            const int tile = part >> 1;
            int idx = part * 256 + tid;
            int r = (idx >> 2) & 127;
            int k8 = idx & 3;
            const __nv_bfloat16* src;
            if (tile == 0)      src = g_A_hi + (((size_t)(m0 + r)) << 8) + k0 + (k8 << 3);
            else if (tile == 1) src = g_A_lo + (((size_t)(m0 + r)) << 8) + k0 + (k8 << 3);
            else if (tile == 2) src = g_W_hi + (((size_t)(n0 + r)) << 8) + k0 + (k8 << 3);
            else                src = g_W_lo + (((size_t)(n0 + r)) << 8) + k0 + (k8 << 3);
            uint4 v = *(const uint4*)src;
            *(uint4*)(smc + tile * XT_TILE + r * XT_ROWB + (k8 << 4)) = v;
        }
        __syncthreads();

#pragma unroll
        for (int ks = 0; ks < 2; ks++) {
            const int kb2 = (ks * 16 + tig * 2) * 2;
            uint32_t a[4][4], bh2[4][2], bl2[4][2];
#pragma unroll
            for (int mf = 0; mf < 4; mf++) {
                const char* base = smc + XT_AHI + (aRow + mf * 16) * XT_ROWB + kb2;
                a[mf][0] = *(const uint32_t*)(base);
                a[mf][1] = *(const uint32_t*)(base + 8 * XT_ROWB);
                a[mf][2] = *(const uint32_t*)(base + 16);
                a[mf][3] = *(const uint32_t*)(base + 8 * XT_ROWB + 16);
            }
#pragma unroll
            for (int nf = 0; nf < 4; nf++) {
                const char* bh_b = smc + XT_BHI + (bRow + nf * 8) * XT_ROWB + kb2;
                bh2[nf][0] = *(const uint32_t*)(bh_b);
                bh2[nf][1] = *(const uint32_t*)(bh_b + 16);
                const char* bl_b = smc + XT_BLO + (bRow + nf * 8) * XT_ROWB + kb2;
                bl2[nf][0] = *(const uint32_t*)(bl_b);
                bl2[nf][1] = *(const uint32_t*)(bl_b + 16);
            }
#pragma unroll
            for (int mf = 0; mf < 4; mf++)
#pragma unroll
                for (int nf = 0; nf < 4; nf++) {
                    mma_bf16(d[mf][nf], a[mf], bh2[nf]);
                    mma_bf16(d[mf][nf], a[mf], bl2[nf]);
                }
#pragma unroll
            for (int mf = 0; mf < 4; mf++) {
                const char* base = smc + XT_ALO + (aRow + mf * 16) * XT_ROWB + kb2;
                a[mf][0] = *(const uint32_t*)(base);
                a[mf][1] = *(const uint32_t*)(base + 8 * XT_ROWB);
                a[mf][2] = *(const uint32_t*)(base + 16);
                a[mf][3] = *(const uint32_t*)(base + 8 * XT_ROWB + 16);
            }
#pragma unroll
            for (int mf = 0; mf < 4; mf++)
#pragma unroll
                for (int nf = 0; nf < 4; nf++)
                    mma_bf16(d[mf][nf], a[mf], bh2[nf]);
        }
        __syncthreads();
    }

    const float* biasS = (const float*)(smc + XT_BIAS);
#pragma unroll
    for (int mf = 0; mf < 4; mf++)
#pragma unroll
        for (int nf = 0; nf < 4; nf++)
#pragma unroll
            for (int r8 = 0; r8 < 2; r8++) {
                int m = m0 + warpM * 64 + mf * 16 + gID + r8 * 8;
                int nl = warpN * 32 + nf * 8 + tig * 2;
                int b_ = m >> 10, s = m & 1023;
                float2 v;
                v.x = d[mf][nf][r8 * 2 + 0] + biasS[nl];
                v.y = d[mf][nf][r8 * 2 + 1] + biasS[nl + 1];
                *(float2*)&g_X[(size_t)((s << 6) + b_) * 1024 + n0 + nl] = v;
            }
}

// =====================================================================
// Phase 2: scan (R12 base) with DEDICATED WAITER WARP + SPLIT S2:
//  - warp 15 (non-tail) polls the mbarrier: it starts polling for step
//    t+1 while the tail warps are still computing tail(t) — wakeup and
//    part of the peer-engine latency now overlap the tail.
//  - S2: tail warps bar.sync 4,512; GEMM warps bar.arrive 4,512
//    (non-blocking) so the waiter reaches its poll immediately.
// =====================================================================
// SMEM float layout:
//   Hsm [2][1024]      at 0     (2048)  h double buffer [p][rblk][b][u]
//   Red [4][8][128]    at 2048  (4096)  [b][ks][row]
//   Stg [2][128]       at 6144  (256)   staging [b][u]
#define SM_OFF_R 2048
#define SM_OFF_S 6144
#define SM_FLOATS 6400

__global__ void __cluster_dims__(8, 1, 1) __launch_bounds__(512, 1)
lstm_scan(const float* __restrict__ h0, const float* __restrict__ c0,
          const float* __restrict__ whi, const float* __restrict__ whf,
          const float* __restrict__ whg, const float* __restrict__ who,
          float* __restrict__ out, int out_size)
{
    __shared__ float sm[SM_FLOATS];
    __shared__ __align__(16) ull mbars[2];
    float* Hsm = sm;
    float* Red = sm + SM_OFF_R;
    float* Stg = sm + SM_OFF_S;

    const int tid = threadIdx.x;
    unsigned rank; asm("mov.u32 %0, %%cluster_ctarank;" : "=r"(rank));
    const int b0 = (blockIdx.x >> 3) * 4;

    // GEMM roles: ks = k-slice (32 floats), j2 = row pair
    const int ks = tid >> 6;                  // 0..7
    const int j2 = tid & 63;                  // rows 2*j2, 2*j2+1
    const int r0 = j2 << 1;
    const int g  = r0 >> 5, uu0 = r0 & 31;

    const float* W = (g == 0) ? whi : (g == 1) ? whf : (g == 2) ? whg : who;

    // weights: 2 rows x 32 floats
    ull w2[32];
#pragma unroll
    for (int r = 0; r < 2; r++) {
        const ulonglong2* wp = (const ulonglong2*)(
            W + (size_t)(((int)rank << 5) + uu0 + r) * 256 + (ks << 5));
#pragma unroll
        for (int c4 = 0; c4 < 8; c4++) {
            ulonglong2 wq = wp[c4];
            w2[r * 16 + 2 * c4]     = wq.x;
            w2[r * 16 + 2 * c4 + 1] = wq.y;
        }
    }

    // h0 into buffer 0, layout [rblk][b][u]
    for (int idx = tid; idx < 1024; idx += 512) {
        int rblk = idx >> 7, b = (idx >> 5) & 3, u = idx & 31;
        Hsm[idx] = h0[(size_t)(b0 + b) * 256 + (rblk << 5) + u];
    }
    // tail roles (tid < 128): cb = warp, cu = lane
    const int cu = tid & 31, cb = (tid >> 5) & 3;
    const int ug = ((int)rank << 5) + cu;
    float c_reg = 0.0f;
    if (tid < 128) c_reg = c0[(size_t)(b0 + cb) * 256 + ug];

    unsigned smem_u32, mbar_base;
    asm("{ .reg .u64 t; cvta.to.shared.u64 t, %1; cvt.u32.u64 %0, t; }"
        : "=r"(smem_u32) : "l"(sm));
    asm("{ .reg .u64 t; cvta.to.shared.u64 t, %1; cvt.u32.u64 %0, t; }"
        : "=r"(mbar_base) : "l"(mbars));
    const unsigned mbar0 = mbar_base;
    const unsigned mbar1 = mbar_base + 8;
    const unsigned stg_u32 = smem_u32 + (SM_OFF_S << 2);

    // peer id for this copy lane (skip self): lanes 0..6 -> the 7 peers
    const int peer = (tid < 7) ? ((tid >= (int)rank) ? tid + 1 : tid) : 0;

    if (tid == 0) {
        asm volatile("mbarrier.init.shared.b64 [%0], 1;" :: "r"(mbar0) : "memory");
        asm volatile("mbarrier.init.shared.b64 [%0], 1;" :: "r"(mbar1) : "memory");
    }
    __syncthreads();
    asm volatile("barrier.cluster.arrive.aligned;" ::: "memory");
    asm volatile("barrier.cluster.wait.aligned;" ::: "memory");

    unsigned ph0 = 0, ph1 = 0;
    float x0 = 0.f, x1 = 0.f, x2 = 0.f, x3 = 0.f;

    for (int t = 0; t < SS; t++) {
        const int p = t & 1;

        // ---- x prefetch (h-independent): issue BEFORE the wait
        if (tid < 128) {
            const float* xp = g_X + (size_t)t * 65536
                            + (size_t)(b0 + cb) * 1024 + ug;
            x0 = xp[0]; x1 = xp[256]; x2 = xp[512]; x3 = xp[768];
        }

        // ---- dedicated waiter: warp 15 polls; __syncthreads releases all
        if (t > 0) {
            if (tid >= 480) {
                const unsigned wb  = p ? mbar1 : mbar0;
                const unsigned phw = p ? ph1 : ph0;
                if (tid == 480)
                    asm volatile("mbarrier.arrive.expect_tx.shared.b64 _, [%0], %1;"
                                 :: "r"(wb), "r"(3584u) : "memory");
                asm volatile("{\n\t.reg .pred P1;\n\t"
                    "LW_%=:\n\t"
                    "mbarrier.try_wait.parity.acquire.cta.shared::cta.b64 P1, [%0], %1, 0x989680;\n\t"
                    "@P1 bra.uni LD_%=;\n\t"
                    "bra.uni LW_%=;\n\t"
                    "LD_%=:\n\t}"
                    :: "r"(wb), "r"(phw) : "memory");
            }
            if (p) ph1 ^= 1; else ph0 ^= 1;
        }
        __syncthreads();   // S1: Hsm[p] complete (peers via waiter acquire, own via STS)

        // ---- GEMM: 2 rows x 4 batches x 32-k slice (broadcast LDS.128)
        {
            const float* hb = Hsm + (p << 10) + (ks << 7);
            ull a00 = 0, a01 = 0, a02 = 0, a03 = 0;
            ull a10 = 0, a11 = 0, a12 = 0, a13 = 0;
#pragma unroll
            for (int c = 0; c < 8; c++) {
                ulonglong2 hq0 = *(const ulonglong2*)(hb + 0 * 32 + (c << 2));
                ulonglong2 hq1 = *(const ulonglong2*)(hb + 1 * 32 + (c << 2));
                ulonglong2 hq2 = *(const ulonglong2*)(hb + 2 * 32 + (c << 2));
                ulonglong2 hq3 = *(const ulonglong2*)(hb + 3 * 32 + (c << 2));
                ull w0lo = w2[2*c], w0hi = w2[2*c+1];
                ull w1lo = w2[16 + 2*c], w1hi = w2[16 + 2*c+1];
                a00 = fma2(w0hi, hq0.y, fma2(w0lo, hq0.x, a00));
                a01 = fma2(w0hi, hq1.y, fma2(w0lo, hq1.x, a01));
                a02 = fma2(w0hi, hq2.y, fma2(w0lo, hq2.x, a02));
                a03 = fma2(w0hi, hq3.y, fma2(w0lo, hq3.x, a03));
                a10 = fma2(w1hi, hq0.y, fma2(w1lo, hq0.x, a10));
                a11 = fma2(w1hi, hq1.y, fma2(w1lo, hq1.x, a11));
                a12 = fma2(w1hi, hq2.y, fma2(w1lo, hq2.x, a12));
                a13 = fma2(w1hi, hq3.y, fma2(w1lo, hq3.x, a13));
            }
            float lo, hi;
            float s00, s01, s02, s03, s10, s11, s12, s13;
            upk2(a00, lo, hi); s00 = lo + hi;
            upk2(a01, lo, hi); s01 = lo + hi;
            upk2(a02, lo, hi); s02 = lo + hi;
            upk2(a03, lo, hi); s03 = lo + hi;
            upk2(a10, lo, hi); s10 = lo + hi;
            upk2(a11, lo, hi); s11 = lo + hi;
            upk2(a12, lo, hi); s12 = lo + hi;
            upk2(a13, lo, hi); s13 = lo + hi;
            float* rp = Red + (ks << 7) + r0;
            *(float2*)(rp + 0 * 1024) = make_float2(s00, s10);
            *(float2*)(rp + 1 * 1024) = make_float2(s01, s11);
            *(float2*)(rp + 2 * 1024) = make_float2(s02, s12);
            *(float2*)(rp + 3 * 1024) = make_float2(s03, s13);
        }

        // ---- S2 split: tail blocks until all 512 arrived; others pass
        if (tid < 128) {
            asm volatile("bar.sync 4, 512;" ::: "memory");
        } else {
            asm volatile("bar.arrive 4, 512;" ::: "memory");
        }

        // ---- tail: reduce, gates, c update, stage + EXCHANGE FIRST
        if (tid < 128) {
            const float* rb = Red + (cb << 10) + cu;
            float pi = 0.f, pf = 0.f, pg = 0.f, po = 0.f;
#pragma unroll
            for (int kk = 0; kk < 8; kk++) {
                const float* rk = rb + (kk << 7);
                pi += rk[0];
                pf += rk[32];
                pg += rk[64];
                po += rk[96];
            }
            pi += x0; pf += x1; pg += x2; po += x3;
            float gi = fast_sigmoid(pi);
            float gf = fast_sigmoid(pf);
            float gg = fast_tanh(pg);
            float go = fast_sigmoid(po);
            c_reg = gf * c_reg + gi * gg;
            float h = go * fast_tanh(c_reg);

            // staging for peers + own block straight into next Hsm
            Stg[(p << 7) + (cb << 5) + cu] = h;
            Hsm[((1 - p) << 10) + ((int)rank << 7) + (cb << 5) + cu] = h;

            // tail-only barrier: staging complete before engine reads it
            asm volatile("bar.sync 1, 128;" ::: "memory");

            // 7 peer copies (lanes 0..6), issued BEFORE out stores
            if (tid < 7 && t < SS - 1) {
                asm volatile("fence.proxy.async.shared::cta;" ::: "memory");
                unsigned dstl = smem_u32 + (((unsigned)(1 - p)) << 12)
                              + ((unsigned)rank << 9);
                unsigned mbl  = p ? mbar0 : mbar1;
                unsigned srcl = stg_u32 + ((unsigned)p << 9);
                unsigned rdst, rmb;
                asm volatile("mapa.shared::cluster.u32 %0, %1, %2;"
                             : "=r"(rdst) : "r"(dstl), "r"(peer));
                asm volatile("mapa.shared::cluster.u32 %0, %1, %2;"
                             : "=r"(rmb) : "r"(mbl), "r"(peer));
                asm volatile(
                    "cp.async.bulk.shared::cluster.shared::cta."
                    "mbarrier::complete_tx::bytes [%0], [%1], 512, [%2];"
                    :: "r"(rdst), "r"(srcl), "r"(rmb) : "memory");
            }

            // out stores: off the inter-CTA critical path
            float h_hi = __shfl_down_sync(0xffffffffu, h, 1);
            if ((cu & 1) == 0) {
                *(float2*)&out[((size_t)(b0 + cb) * 1024 + t) * 256 + ug] =
                    make_float2(h, h_hi);
            }
            if (t == SS - 1) {
                size_t basee = (size_t)BB * SS * HH;
                if (out_size >= (int)(basee + 2u * BB * HH)) {
                    out[basee + (size_t)(b0 + cb) * 256 + ug] = h;
                    out[basee + (size_t)BB * HH + (size_t)(b0 + cb) * 256 + ug] = c_reg;
                }
            }
        }
    }
}

// =====================================================================
extern "C" void kernel_launch(void* const* d_in, const int* in_sizes, int n_in,
                              void* d_out, int out_size)
{
    (void)in_sizes; (void)n_in;
    const float* inputs = (const float*)d_in[0];
    const float* h0     = (const float*)d_in[1];
    const float* c0     = (const float*)d_in[2];
    const float* w_ii   = (const float*)d_in[3];
    const float* w_if   = (const float*)d_in[4];
    const float* w_ig   = (const float*)d_in[5];
    const float* w_io   = (const float*)d_in[6];
    const float* b_ii   = (const float*)d_in[7];
    const float* b_if   = (const float*)d_in[8];
    const float* b_ig   = (const float*)d_in[9];
    const float* b_io   = (const float*)d_in[10];
    const float* w_hi   = (const float*)d_in[11];
    const float* w_hf   = (const float*)d_in[12];
    const float* w_hg   = (const float*)d_in[13];
    const float* w_ho   = (const float*)d_in[14];
    const float* b_hi   = (const float*)d_in[15];
    const float* b_hf   = (const float*)d_in[16];
    const float* b_hg   = (const float*)d_in[17];
    const float* b_ho   = (const float*)d_in[18];
    float* out = (float*)d_out;

    __nv_bfloat16 *ahi, *alo, *whi_p, *wlo_p;
    cudaGetSymbolAddress((void**)&ahi,   g_A_hi);
    cudaGetSymbolAddress((void**)&alo,   g_A_lo);
    cudaGetSymbolAddress((void**)&whi_p, g_W_hi);
    cudaGetSymbolAddress((void**)&wlo_p, g_W_lo);

    cvt_split<<<2048, 256>>>(inputs, ahi, alo, (BB * SS * II) / 4);
    cvt_split<<<64, 256>>>(w_ii, whi_p + 0 * 65536, wlo_p + 0 * 65536, 65536 / 4);
    cvt_split<<<64, 256>>>(w_if, whi_p + 1 * 65536, wlo_p + 1 * 65536, 65536 / 4);
    cvt_split<<<64, 256>>>(w_ig, whi_p + 2 * 65536, wlo_p + 2 * 65536, 65536 / 4);
    cvt_split<<<64, 256>>>(w_io, whi_p + 3 * 65536, wlo_p + 3 * 65536, 65536 / 4);

    lstm_xproj_tc<<<dim3(8, 512), 256>>>(
        b_ii, b_if, b_ig, b_io, b_hi, b_hf, b_hg, b_ho);

    lstm_scan<<<128, 512>>>(
        h0, c0, w_hi, w_hf, w_hg, w_ho, out, out_size);
}

// round 15
// speedup vs baseline: 1.4516x; 1.1520x over previous
#include <cuda_runtime.h>
#include <cuda_bf16.h>
#include <cstdint>
#include <cstddef>

typedef unsigned long long ull;

// Problem constants
#define BB 64
#define SS 1024
#define II 256
#define HH 256

// Scratch: X gate pre-activations [S][B][4*H] fp32, biases included. 256MB.
__device__ float g_X[(size_t)SS * BB * 4 * HH];
// Split-bf16 planes of A (inputs, [B*S][I]) and W (4 gates concat, [1024][256]).
__device__ __nv_bfloat16 g_A_hi[(size_t)BB * SS * II];
__device__ __nv_bfloat16 g_A_lo[(size_t)BB * SS * II];
__device__ __nv_bfloat16 g_W_hi[4 * HH * II];
__device__ __nv_bfloat16 g_W_lo[4 * HH * II];
// Split-bf16 planes of the recurrent weights (4 gates concat, [1024][256]).
__device__ __nv_bfloat16 g_Wh_hi[4 * HH * HH];
__device__ __nv_bfloat16 g_Wh_lo[4 * HH * HH];

// Accurate fast activations (ex2/rcp approx: ~2^-22 rel err, >> 1e-3 budget)
__device__ __forceinline__ float fast_sigmoid(float x) {
    float e; asm("ex2.approx.f32 %0, %1;" : "=f"(e) : "f"(-x * 1.4426950408889634f));
    float r; asm("rcp.approx.f32 %0, %1;" : "=f"(r) : "f"(1.0f + e));
    return r;
}
__device__ __forceinline__ float fast_tanh(float x) {
    x = fminf(15.0f, fmaxf(-15.0f, x));
    float e; asm("ex2.approx.f32 %0, %1;" : "=f"(e) : "f"(x * 2.8853900817779268f)); // e^{2x}
    float r; asm("rcp.approx.f32 %0, %1;" : "=f"(r) : "f"(e + 1.0f));
    return fmaf(-2.0f, r, 1.0f);
}

// ---------------- warp-level bf16 HMMA -----------------------------------
__device__ __forceinline__ void mma_bf16(float* d, const uint32_t* a,
                                         const uint32_t* b) {
    asm volatile(
        "mma.sync.aligned.m16n8k16.row.col.f32.bf16.bf16.f32 "
        "{%0,%1,%2,%3}, {%4,%5,%6,%7}, {%8,%9}, {%0,%1,%2,%3};"
        : "+f"(d[0]), "+f"(d[1]), "+f"(d[2]), "+f"(d[3])
        : "r"(a[0]), "r"(a[1]), "r"(a[2]), "r"(a[3]), "r"(b[0]), "r"(b[1]));
}

// =====================================================================
// Split-bf16 conversion:  x -> (hi, lo) with x = hi + lo + O(2^-18 x)
// =====================================================================
__global__ void cvt_split(const float* __restrict__ src,
                          __nv_bfloat16* __restrict__ hi,
                          __nv_bfloat16* __restrict__ lo, int n4)
{
    int i = blockIdx.x * blockDim.x + threadIdx.x;
    int stride = gridDim.x * blockDim.x;
    for (; i < n4; i += stride) {
        float4 v = ((const float4*)src)[i];
        float f[4] = {v.x, v.y, v.z, v.w};
        unsigned short hb[4], lb[4];
#pragma unroll
        for (int c = 0; c < 4; c++) {
            __nv_bfloat16 h = __float2bfloat16(f[c]);
            float hf = __bfloat162float(h);
            __nv_bfloat16 l = __float2bfloat16(f[c] - hf);
            hb[c] = __bfloat16_as_ushort(h);
            lb[c] = __bfloat16_as_ushort(l);
        }
        ((ushort4*)hi)[i] = make_ushort4(hb[0], hb[1], hb[2], hb[3]);
        ((ushort4*)lo)[i] = make_ushort4(lb[0], lb[1], lb[2], lb[3]);
    }
}

// =====================================================================
// Phase 1 (tensor pipe, warp HMMA): X = inputs . W^T + bias, 3-term
// bf16 split. UNCHANGED (passed, ~300us).
// =====================================================================
#define XT_ROWB 80
#define XT_TILE (128 * XT_ROWB)
#define XT_AHI 0
#define XT_ALO (1 * XT_TILE)
#define XT_BHI (2 * XT_TILE)
#define XT_BLO (3 * XT_TILE)
#define XT_BIAS (4 * XT_TILE)
#define XT_SMEM (XT_BIAS + 512)

__global__ void __launch_bounds__(256, 2) lstm_xproj_tc(
    const float* __restrict__ bii, const float* __restrict__ bif_,
    const float* __restrict__ big_, const float* __restrict__ bio,
    const float* __restrict__ bhi, const float* __restrict__ bhf,
    const float* __restrict__ bhg, const float* __restrict__ bho)
{
    __shared__ char smc[XT_SMEM];
    const int tid = threadIdx.x;
    const int lane = tid & 31, wid = tid >> 5;
    const int warpM = wid >> 2, warpN = wid & 3;
    const int gID = lane >> 2, tig = lane & 3;
    const int n0 = blockIdx.x << 7;
    const int m0 = blockIdx.y << 7;

    if (tid < 128) {
        int n = n0 + tid;
        int g = n >> 8, u = n & 255;
        const float* bi = (g == 0) ? bii : (g == 1) ? bif_ : (g == 2) ? big_ : bio;
        const float* bh = (g == 0) ? bhi : (g == 1) ? bhf : (g == 2) ? bhg : bho;
        ((float*)(smc + XT_BIAS))[tid] = bi[u] + bh[u];
    }

    float d[4][4][4];
#pragma unroll
    for (int mf = 0; mf < 4; mf++)
#pragma unroll
        for (int nf = 0; nf < 4; nf++)
#pragma unroll
            for (int c = 0; c < 4; c++) d[mf][nf][c] = 0.0f;

    const int aRow = warpM * 64 + gID;
    const int bRow = warpN * 32 + gID;

#pragma unroll 1
    for (int ch = 0; ch < 8; ch++) {
        const int k0 = ch << 5;
#pragma unroll
        for (int part = 0; part < 8; part++) {
            const int tile = part >> 1;
            int idx = part * 256 + tid;
            int r = (idx >> 2) & 127;
            int k8 = idx & 3;
            const __nv_bfloat16* src;
            if (tile == 0)      src = g_A_hi + (((size_t)(m0 + r)) << 8) + k0 + (k8 << 3);
            else if (tile == 1) src = g_A_lo + (((size_t)(m0 + r)) << 8) + k0 + (k8 << 3);
            else if (tile == 2) src = g_W_hi + (((size_t)(n0 + r)) << 8) + k0 + (k8 << 3);
            else                src = g_W_lo + (((size_t)(n0 + r)) << 8) + k0 + (k8 << 3);
            uint4 v = *(const uint4*)src;
            *(uint4*)(smc + tile * XT_TILE + r * XT_ROWB + (k8 << 4)) = v;
        }
        __syncthreads();

#pragma unroll
        for (int ks = 0; ks < 2; ks++) {
            const int kb2 = (ks * 16 + tig * 2) * 2;
            uint32_t a[4][4], bh2[4][2], bl2[4][2];
#pragma unroll
            for (int mf = 0; mf < 4; mf++) {
                const char* base = smc + XT_AHI + (aRow + mf * 16) * XT_ROWB + kb2;
                a[mf][0] = *(const uint32_t*)(base);
                a[mf][1] = *(const uint32_t*)(base + 8 * XT_ROWB);
                a[mf][2] = *(const uint32_t*)(base + 16);
                a[mf][3] = *(const uint32_t*)(base + 8 * XT_ROWB + 16);
            }
#pragma unroll
            for (int nf = 0; nf < 4; nf++) {
                const char* bh_b = smc + XT_BHI + (bRow + nf * 8) * XT_ROWB + kb2;
                bh2[nf][0] = *(const uint32_t*)(bh_b);
                bh2[nf][1] = *(const uint32_t*)(bh_b + 16);
                const char* bl_b = smc + XT_BLO + (bRow + nf * 8) * XT_ROWB + kb2;
                bl2[nf][0] = *(const uint32_t*)(bl_b);
                bl2[nf][1] = *(const uint32_t*)(bl_b + 16);
            }
#pragma unroll
            for (int mf = 0; mf < 4; mf++)
#pragma unroll
                for (int nf = 0; nf < 4; nf++) {
                    mma_bf16(d[mf][nf], a[mf], bh2[nf]);
                    mma_bf16(d[mf][nf], a[mf], bl2[nf]);
                }
#pragma unroll
            for (int mf = 0; mf < 4; mf++) {
                const char* base = smc + XT_ALO + (aRow + mf * 16) * XT_ROWB + kb2;
                a[mf][0] = *(const uint32_t*)(base);
                a[mf][1] = *(const uint32_t*)(base + 8 * XT_ROWB);
                a[mf][2] = *(const uint32_t*)(base + 16);
                a[mf][3] = *(const uint32_t*)(base + 8 * XT_ROWB + 16);
            }
#pragma unroll
            for (int mf = 0; mf < 4; mf++)
#pragma unroll
                for (int nf = 0; nf < 4; nf++)
                    mma_bf16(d[mf][nf], a[mf], bh2[nf]);
        }
        __syncthreads();
    }

    const float* biasS = (const float*)(smc + XT_BIAS);
#pragma unroll
    for (int mf = 0; mf < 4; mf++)
#pragma unroll
        for (int nf = 0; nf < 4; nf++)
#pragma unroll
            for (int r8 = 0; r8 < 2; r8++) {
                int m = m0 + warpM * 64 + mf * 16 + gID + r8 * 8;
                int nl = warpN * 32 + nf * 8 + tig * 2;
                int b_ = m >> 10, s = m & 1023;
                float2 v;
                v.x = d[mf][nf][r8 * 2 + 0] + biasS[nl];
                v.y = d[mf][nf][r8 * 2 + 1] + biasS[nl + 1];
                *(float2*)&g_X[(size_t)((s << 6) + b_) * 1024 + n0 + nl] = v;
            }
}

// =====================================================================
// Phase 2: scan on TENSOR CORES. 16 clusters x 8 CTAs, 4 batches per
// cluster, 128 weight rows per CTA. 512 threads = 16 warps:
//   warp w: M = rows (w&7)*16..+15, K-half = w>>3 (k in [half*128,+128))
//   A (weights) = static bf16-split fragments in registers (64 u32)
//   B (h) = bf16-split planes in fragment-native SMEM layout:
//     Hsm2[parity][rblk(8)][plane(2)][n(4)][tig(4)][ks1(2)][bsel(2)][jj(2)]
//     -> one LDS.128 per (rblk, plane) yields B frags for 2 k-steps.
//   3-term split: AhiBhi + AhiBlo + AloBhi, fp32 accum, 24 HMMA/warp.
//   2-way k reduction through Red[2][128][5] fp32 (pad-5: conflict-free).
// Tail (warps 0-3): gates, c update, h -> (hi,lo) bf16, stage, 7x512B
// cluster bulk copies (expect_tx 3584), own block via local STS.
// Waiter = warp 15 (R14 scheme), split S2 barrier.
// =====================================================================
// smB byte map:
//   [0, 8192)      Hsm2 (2 parities x 4096)
//   [8192, 13312)  Red (2 halves x 128 rows x 5 floats)
//   [13312, 14336) Stg (2 parities x 512B)
#define SC_RED 8192
#define SC_STG 13312
#define SC_BYTES 14848

__global__ void __cluster_dims__(8, 1, 1) __launch_bounds__(512, 1)
lstm_scan(const float* __restrict__ h0, const float* __restrict__ c0,
          float* __restrict__ out, int out_size)
{
    __shared__ __align__(16) char smB[SC_BYTES];
    __shared__ __align__(16) ull mbars[2];

    const int tid = threadIdx.x;
    const int lane = tid & 31, w = tid >> 5;
    const int gID = lane >> 2, tig = lane & 3;
    unsigned rank; asm("mov.u32 %0, %%cluster_ctarank;" : "=r"(rank));
    const int b0 = (blockIdx.x >> 3) * 4;

    const int khalf = w >> 3, w7 = w & 7;
    const int mrow0 = w7 << 4;                 // warp's first row (0..112)
    const int gate  = w7 >> 1;
    const int uu0   = (w7 & 1) << 4;

    // ---- static A fragments (weights, bf16 split) into registers
    uint32_t waH[8][4], waL[8][4];
    {
        const size_t r0 = (size_t)(gate * 256 + ((int)rank << 5) + uu0 + gID) * 256;
        const size_t r1 = r0 + 8 * 256;
#pragma unroll
        for (int q = 0; q < 8; q++) {
            int kk = (khalf * 8 + q) * 16 + tig * 2;
            waH[q][0] = *(const uint32_t*)(g_Wh_hi + r0 + kk);
            waH[q][1] = *(const uint32_t*)(g_Wh_hi + r1 + kk);
            waH[q][2] = *(const uint32_t*)(g_Wh_hi + r0 + kk + 8);
            waH[q][3] = *(const uint32_t*)(g_Wh_hi + r1 + kk + 8);
            waL[q][0] = *(const uint32_t*)(g_Wh_lo + r0 + kk);
            waL[q][1] = *(const uint32_t*)(g_Wh_lo + r1 + kk);
            waL[q][2] = *(const uint32_t*)(g_Wh_lo + r0 + kk + 8);
            waL[q][3] = *(const uint32_t*)(g_Wh_lo + r1 + kk + 8);
        }
    }

    // ---- h0 -> bf16 split planes into Hsm2[parity 0]
    for (int e = tid; e < 1024; e += 512) {
        int b = e >> 8, k = e & 255;
        float v = h0[(size_t)(b0 + b) * 256 + k];
        __nv_bfloat16 hi = __float2bfloat16(v);
        __nv_bfloat16 lo = __float2bfloat16(v - __bfloat162float(hi));
        int rblk = k >> 5, kq = k & 31;
        int ks1 = kq >> 4, rr = kq & 15;
        int tg = (rr >> 1) & 3, bs = rr >> 3, jj = rr & 1;
        int off = rblk * 512 + b * 64 + tg * 16 + ks1 * 8 + bs * 4 + jj * 2;
        *(__nv_bfloat16*)(smB + off) = hi;
        *(__nv_bfloat16*)(smB + off + 256) = lo;
    }

    // tail roles (tid < 128): cu = lane, cb = warp
    const int cu = tid & 31, cb = (tid >> 5) & 3;
    const int ug = ((int)rank << 5) + cu;
    float c_reg = 0.0f;
    if (tid < 128) c_reg = c0[(size_t)(b0 + cb) * 256 + ug];
    // staging offset for this tail thread (within a 512B plane-pair block)
    int st_off;
    {
        int ks1 = cu >> 4, rr = cu & 15;
        int tg = (rr >> 1) & 3, bs = rr >> 3, jj = rr & 1;
        st_off = cb * 64 + tg * 16 + ks1 * 8 + bs * 4 + jj * 2;
    }

    unsigned smem_u32, mbar_base;
    asm("{ .reg .u64 t; cvta.to.shared.u64 t, %1; cvt.u32.u64 %0, t; }"
        : "=r"(smem_u32) : "l"(smB));
    asm("{ .reg .u64 t; cvta.to.shared.u64 t, %1; cvt.u32.u64 %0, t; }"
        : "=r"(mbar_base) : "l"(mbars));
    const unsigned mbar0 = mbar_base;
    const unsigned mbar1 = mbar_base + 8;

    const int peer = (tid < 7) ? ((tid >= (int)rank) ? tid + 1 : tid) : 0;

    if (tid == 0) {
        asm volatile("mbarrier.init.shared.b64 [%0], 1;" :: "r"(mbar0) : "memory");
        asm volatile("mbarrier.init.shared.b64 [%0], 1;" :: "r"(mbar1) : "memory");
    }
    __syncthreads();
    asm volatile("barrier.cluster.arrive.aligned;" ::: "memory");
    asm volatile("barrier.cluster.wait.aligned;" ::: "memory");

    unsigned ph0 = 0, ph1 = 0;
    float x0 = 0.f, x1 = 0.f, x2 = 0.f, x3 = 0.f;

    for (int t = 0; t < SS; t++) {
        const int p = t & 1;

        // ---- x prefetch (h-independent): issue BEFORE the wait
        if (tid < 128) {
            const float* xp = g_X + (size_t)t * 65536
                            + (size_t)(b0 + cb) * 1024 + ug;
            x0 = xp[0]; x1 = xp[256]; x2 = xp[512]; x3 = xp[768];
        }

        // ---- dedicated waiter: warp 15 polls; __syncthreads releases all
        if (t > 0) {
            if (tid >= 480) {
                const unsigned wb  = p ? mbar1 : mbar0;
                const unsigned phw = p ? ph1 : ph0;
                if (tid == 480)
                    asm volatile("mbarrier.arrive.expect_tx.shared.b64 _, [%0], %1;"
                                 :: "r"(wb), "r"(3584u) : "memory");
                asm volatile("{\n\t.reg .pred P1;\n\t"
                    "LW_%=:\n\t"
                    "mbarrier.try_wait.parity.acquire.cta.shared::cta.b64 P1, [%0], %1, 0x989680;\n\t"
                    "@P1 bra.uni LD_%=;\n\t"
                    "bra.uni LW_%=;\n\t"
                    "LD_%=:\n\t}"
                    :: "r"(wb), "r"(phw) : "memory");
            }
            if (p) ph1 ^= 1; else ph0 ^= 1;
        }
        __syncthreads();   // S1: Hsm2[p] complete

        // ---- GEMM on tensor cores: 24 HMMA, B frags via 8 LDS.128
        {
            const char* hb = smB + (p << 12) + gID * 64 + tig * 16;
            float cA[4] = {0.f, 0.f, 0.f, 0.f};
            float cBv[4] = {0.f, 0.f, 0.f, 0.f};
#pragma unroll
            for (int rb = 0; rb < 4; rb++) {
                const char* blk = hb + ((khalf * 4 + rb) << 9);
                uint4 BH = *(const uint4*)blk;
                uint4 BL = *(const uint4*)(blk + 256);
                const int q = rb * 2;
                {
                    uint32_t bh[2] = {BH.x, BH.y};
                    uint32_t bl[2] = {BL.x, BL.y};
                    mma_bf16(cA,  waH[q], bh);
                    mma_bf16(cBv, waH[q], bl);
                    mma_bf16(cBv, waL[q], bh);
                }
                {
                    uint32_t bh[2] = {BH.z, BH.w};
                    uint32_t bl[2] = {BL.z, BL.w};
                    mma_bf16(cA,  waH[q + 1], bh);
                    mma_bf16(cA,  waL[q + 1], bh);
                    mma_bf16(cBv, waH[q + 1], bl);
                }
            }
            if (tig < 2) {
                float* rf = (float*)(smB + SC_RED) + khalf * 640;
                const int row = mrow0 + gID;
                rf[row * 5 + tig * 2]           = cA[0] + cBv[0];
                rf[row * 5 + tig * 2 + 1]       = cA[1] + cBv[1];
                rf[(row + 8) * 5 + tig * 2]     = cA[2] + cBv[2];
                rf[(row + 8) * 5 + tig * 2 + 1] = cA[3] + cBv[3];
            }
        }

        // ---- S2 split: tail blocks until all 512 arrived; others pass
        if (tid < 128) {
            asm volatile("bar.sync 4, 512;" ::: "memory");
        } else {
            asm volatile("bar.arrive 4, 512;" ::: "memory");
        }

        // ---- tail: reduce 2 halves, gates, c update, stage + exchange
        if (tid < 128) {
            const float* rf = (float*)(smB + SC_RED);
            float pi = rf[(0 * 32 + cu) * 5 + cb] + rf[640 + (0 * 32 + cu) * 5 + cb];
            float pf = rf[(1 * 32 + cu) * 5 + cb] + rf[640 + (1 * 32 + cu) * 5 + cb];
            float pg = rf[(2 * 32 + cu) * 5 + cb] + rf[640 + (2 * 32 + cu) * 5 + cb];
            float po = rf[(3 * 32 + cu) * 5 + cb] + rf[640 + (3 * 32 + cu) * 5 + cb];
            pi += x0; pf += x1; pg += x2; po += x3;
            float gi = fast_sigmoid(pi);
            float gf = fast_sigmoid(pf);
            float gg = fast_tanh(pg);
            float go = fast_sigmoid(po);
            c_reg = gf * c_reg + gi * gg;
            float h = go * fast_tanh(c_reg);

            // convert h to bf16 split; stage for peers + own block local
            __nv_bfloat16 hhi = __float2bfloat16(h);
            __nv_bfloat16 hlo = __float2bfloat16(h - __bfloat162float(hhi));
            {
                char* sp = smB + SC_STG + (p << 9);
                *(__nv_bfloat16*)(sp + st_off) = hhi;
                *(__nv_bfloat16*)(sp + st_off + 256) = hlo;
                char* hp = smB + ((1 - p) << 12) + ((int)rank << 9);
                *(__nv_bfloat16*)(hp + st_off) = hhi;
                *(__nv_bfloat16*)(hp + st_off + 256) = hlo;
            }

            asm volatile("bar.sync 1, 128;" ::: "memory");

            if (tid < 7 && t < SS - 1) {
                asm volatile("fence.proxy.async.shared::cta;" ::: "memory");
                unsigned dstl = smem_u32 + (((unsigned)(1 - p)) << 12)
                              + ((unsigned)rank << 9);
                unsigned mbl  = p ? mbar0 : mbar1;
                unsigned srcl = smem_u32 + SC_STG + ((unsigned)p << 9);
                unsigned rdst, rmb;
                asm volatile("mapa.shared::cluster.u32 %0, %1, %2;"
                             : "=r"(rdst) : "r"(dstl), "r"(peer));
                asm volatile("mapa.shared::cluster.u32 %0, %1, %2;"
                             : "=r"(rmb) : "r"(mbl), "r"(peer));
                asm volatile(
                    "cp.async.bulk.shared::cluster.shared::cta."
                    "mbarrier::complete_tx::bytes [%0], [%1], 512, [%2];"
                    :: "r"(rdst), "r"(srcl), "r"(rmb) : "memory");
            }

            // out stores: off the inter-CTA critical path
            float h_hi2 = __shfl_down_sync(0xffffffffu, h, 1);
            if ((cu & 1) == 0) {
                *(float2*)&out[((size_t)(b0 + cb) * 1024 + t) * 256 + ug] =
                    make_float2(h, h_hi2);
            }
            if (t == SS - 1) {
                size_t basee = (size_t)BB * SS * HH;
                if (out_size >= (int)(basee + 2u * BB * HH)) {
                    out[basee + (size_t)(b0 + cb) * 256 + ug] = h;
                    out[basee + (size_t)BB * HH + (size_t)(b0 + cb) * 256 + ug] = c_reg;
                }
            }
        }
    }
}

// =====================================================================
extern "C" void kernel_launch(void* const* d_in, const int* in_sizes, int n_in,
                              void* d_out, int out_size)
{
    (void)in_sizes; (void)n_in;
    const float* inputs = (const float*)d_in[0];
    const float* h0     = (const float*)d_in[1];
    const float* c0     = (const float*)d_in[2];
    const float* w_ii   = (const float*)d_in[3];
    const float* w_if   = (const float*)d_in[4];
    const float* w_ig   = (const float*)d_in[5];
    const float* w_io   = (const float*)d_in[6];
    const float* b_ii   = (const float*)d_in[7];
    const float* b_if   = (const float*)d_in[8];
    const float* b_ig   = (const float*)d_in[9];
    const float* b_io   = (const float*)d_in[10];
    const float* w_hi   = (const float*)d_in[11];
    const float* w_hf   = (const float*)d_in[12];
    const float* w_hg   = (const float*)d_in[13];
    const float* w_ho   = (const float*)d_in[14];
    const float* b_hi   = (const float*)d_in[15];
    const float* b_hf   = (const float*)d_in[16];
    const float* b_hg   = (const float*)d_in[17];
    const float* b_ho   = (const float*)d_in[18];
    float* out = (float*)d_out;

    __nv_bfloat16 *ahi, *alo, *whi_p, *wlo_p, *whh, *whl;
    cudaGetSymbolAddress((void**)&ahi,   g_A_hi);
    cudaGetSymbolAddress((void**)&alo,   g_A_lo);
    cudaGetSymbolAddress((void**)&whi_p, g_W_hi);
    cudaGetSymbolAddress((void**)&wlo_p, g_W_lo);
    cudaGetSymbolAddress((void**)&whh,   g_Wh_hi);
    cudaGetSymbolAddress((void**)&whl,   g_Wh_lo);

    cvt_split<<<2048, 256>>>(inputs, ahi, alo, (BB * SS * II) / 4);
    cvt_split<<<64, 256>>>(w_ii, whi_p + 0 * 65536, wlo_p + 0 * 65536, 65536 / 4);
    cvt_split<<<64, 256>>>(w_if, whi_p + 1 * 65536, wlo_p + 1 * 65536, 65536 / 4);
    cvt_split<<<64, 256>>>(w_ig, whi_p + 2 * 65536, wlo_p + 2 * 65536, 65536 / 4);
    cvt_split<<<64, 256>>>(w_io, whi_p + 3 * 65536, wlo_p + 3 * 65536, 65536 / 4);
    cvt_split<<<64, 256>>>(w_hi, whh + 0 * 65536, whl + 0 * 65536, 65536 / 4);
    cvt_split<<<64, 256>>>(w_hf, whh + 1 * 65536, whl + 1 * 65536, 65536 / 4);
    cvt_split<<<64, 256>>>(w_hg, whh + 2 * 65536, whl + 2 * 65536, 65536 / 4);
    cvt_split<<<64, 256>>>(w_ho, whh + 3 * 65536, whl + 3 * 65536, 65536 / 4);

    lstm_xproj_tc<<<dim3(8, 512), 256>>>(
        b_ii, b_if, b_ig, b_io, b_hi, b_hf, b_hg, b_ho);

    lstm_scan<<<128, 512>>>(h0, c0, out, out_size);
}

// round 16
// speedup vs baseline: 1.5311x; 1.0547x over previous
#include <cuda_runtime.h>
#include <cuda_bf16.h>
#include <cstdint>
#include <cstddef>

typedef unsigned long long ull;

// Problem constants
#define BB 64
#define SS 1024
#define II 256
#define HH 256

// Scratch: X gate pre-activations [S][B][4*H] fp32, biases included. 256MB.
__device__ float g_X[(size_t)SS * BB * 4 * HH];
// Split-bf16 planes of A (inputs, [B*S][I]) and W (4 gates concat, [1024][256]).
__device__ __nv_bfloat16 g_A_hi[(size_t)BB * SS * II];
__device__ __nv_bfloat16 g_A_lo[(size_t)BB * SS * II];
__device__ __nv_bfloat16 g_W_hi[4 * HH * II];
__device__ __nv_bfloat16 g_W_lo[4 * HH * II];
// Split-bf16 planes of the recurrent weights (4 gates concat, [1024][256]).
__device__ __nv_bfloat16 g_Wh_hi[4 * HH * HH];
__device__ __nv_bfloat16 g_Wh_lo[4 * HH * HH];

// Accurate fast activations (ex2/rcp approx: ~2^-22 rel err, >> 1e-3 budget)
__device__ __forceinline__ float fast_sigmoid(float x) {
    float e; asm("ex2.approx.f32 %0, %1;" : "=f"(e) : "f"(-x * 1.4426950408889634f));
    float r; asm("rcp.approx.f32 %0, %1;" : "=f"(r) : "f"(1.0f + e));
    return r;
}
__device__ __forceinline__ float fast_tanh(float x) {
    x = fminf(15.0f, fmaxf(-15.0f, x));
    float e; asm("ex2.approx.f32 %0, %1;" : "=f"(e) : "f"(x * 2.8853900817779268f)); // e^{2x}
    float r; asm("rcp.approx.f32 %0, %1;" : "=f"(r) : "f"(e + 1.0f));
    return fmaf(-2.0f, r, 1.0f);
}

// ---------------- warp-level bf16 HMMA -----------------------------------
__device__ __forceinline__ void mma_bf16(float* d, const uint32_t* a,
                                         const uint32_t* b) {
    asm volatile(
        "mma.sync.aligned.m16n8k16.row.col.f32.bf16.bf16.f32 "
        "{%0,%1,%2,%3}, {%4,%5,%6,%7}, {%8,%9}, {%0,%1,%2,%3};"
        : "+f"(d[0]), "+f"(d[1]), "+f"(d[2]), "+f"(d[3])
        : "r"(a[0]), "r"(a[1]), "r"(a[2]), "r"(a[3]), "r"(b[0]), "r"(b[1]));
}

// =====================================================================
// Split-bf16 conversion:  x -> (hi, lo) with x = hi + lo + O(2^-18 x)
// =====================================================================
__global__ void cvt_split(const float* __restrict__ src,
                          __nv_bfloat16* __restrict__ hi,
                          __nv_bfloat16* __restrict__ lo, int n4)
{
    int i = blockIdx.x * blockDim.x + threadIdx.x;
    int stride = gridDim.x * blockDim.x;
    for (; i < n4; i += stride) {
        float4 v = ((const float4*)src)[i];
        float f[4] = {v.x, v.y, v.z, v.w};
        unsigned short hb[4], lb[4];
#pragma unroll
        for (int c = 0; c < 4; c++) {
            __nv_bfloat16 h = __float2bfloat16(f[c]);
            float hf = __bfloat162float(h);
            __nv_bfloat16 l = __float2bfloat16(f[c] - hf);
            hb[c] = __bfloat16_as_ushort(h);
            lb[c] = __bfloat16_as_ushort(l);
        }
        ((ushort4*)hi)[i] = make_ushort4(hb[0], hb[1], hb[2], hb[3]);
        ((ushort4*)lo)[i] = make_ushort4(lb[0], lb[1], lb[2], lb[3]);
    }
}

// =====================================================================
// Phase 1 (tensor pipe, warp HMMA): X = inputs . W^T + bias, 3-term
// bf16 split. UNCHANGED (passed, ~300us).
// =====================================================================
#define XT_ROWB 80
#define XT_TILE (128 * XT_ROWB)
#define XT_AHI 0
#define XT_ALO (1 * XT_TILE)
#define XT_BHI (2 * XT_TILE)
#define XT_BLO (3 * XT_TILE)
#define XT_BIAS (4 * XT_TILE)
#define XT_SMEM (XT_BIAS + 512)

__global__ void __launch_bounds__(256, 2) lstm_xproj_tc(
    const float* __restrict__ bii, const float* __restrict__ bif_,
    const float* __restrict__ big_, const float* __restrict__ bio,
    const float* __restrict__ bhi, const float* __restrict__ bhf,
    const float* __restrict__ bhg, const float* __restrict__ bho)
{
    __shared__ char smc[XT_SMEM];
    const int tid = threadIdx.x;
    const int lane = tid & 31, wid = tid >> 5;
    const int warpM = wid >> 2, warpN = wid & 3;
    const int gID = lane >> 2, tig = lane & 3;
    const int n0 = blockIdx.x << 7;
    const int m0 = blockIdx.y << 7;

    if (tid < 128) {
        int n = n0 + tid;
        int g = n >> 8, u = n & 255;
        const float* bi = (g == 0) ? bii : (g == 1) ? bif_ : (g == 2) ? big_ : bio;
        const float* bh = (g == 0) ? bhi : (g == 1) ? bhf : (g == 2) ? bhg : bho;
        ((float*)(smc + XT_BIAS))[tid] = bi[u] + bh[u];
    }

    float d[4][4][4];
#pragma unroll
    for (int mf = 0; mf < 4; mf++)
#pragma unroll
        for (int nf = 0; nf < 4; nf++)
#pragma unroll
            for (int c = 0; c < 4; c++) d[mf][nf][c] = 0.0f;

    const int aRow = warpM * 64 + gID;
    const int bRow = warpN * 32 + gID;

#pragma unroll 1
    for (int ch = 0; ch < 8; ch++) {
        const int k0 = ch << 5;
#pragma unroll
        for (int part = 0; part < 8; part++) {
            const int tile = part >> 1;
            int idx = part * 256 + tid;
            int r = (idx >> 2) & 127;
            int k8 = idx & 3;
            const __nv_bfloat16* src;
            if (tile == 0)      src = g_A_hi + (((size_t)(m0 + r)) << 8) + k0 + (k8 << 3);
            else if (tile == 1) src = g_A_lo + (((size_t)(m0 + r)) << 8) + k0 + (k8 << 3);
            else if (tile == 2) src = g_W_hi + (((size_t)(n0 + r)) << 8) + k0 + (k8 << 3);
            else                src = g_W_lo + (((size_t)(n0 + r)) << 8) + k0 + (k8 << 3);
            uint4 v = *(const uint4*)src;
            *(uint4*)(smc + tile * XT_TILE + r * XT_ROWB + (k8 << 4)) = v;
        }
        __syncthreads();

#pragma unroll
        for (int ks = 0; ks < 2; ks++) {
            const int kb2 = (ks * 16 + tig * 2) * 2;
            uint32_t a[4][4], bh2[4][2], bl2[4][2];
#pragma unroll
            for (int mf = 0; mf < 4; mf++) {
                const char* base = smc + XT_AHI + (aRow + mf * 16) * XT_ROWB + kb2;
                a[mf][0] = *(const uint32_t*)(base);
                a[mf][1] = *(const uint32_t*)(base + 8 * XT_ROWB);
                a[mf][2] = *(const uint32_t*)(base + 16);
                a[mf][3] = *(const uint32_t*)(base + 8 * XT_ROWB + 16);
            }
#pragma unroll
            for (int nf = 0; nf < 4; nf++) {
                const char* bh_b = smc + XT_BHI + (bRow + nf * 8) * XT_ROWB + kb2;
                bh2[nf][0] = *(const uint32_t*)(bh_b);
                bh2[nf][1] = *(const uint32_t*)(bh_b + 16);
                const char* bl_b = smc + XT_BLO + (bRow + nf * 8) * XT_ROWB + kb2;
                bl2[nf][0] = *(const uint32_t*)(bl_b);
                bl2[nf][1] = *(const uint32_t*)(bl_b + 16);
            }
#pragma unroll
            for (int mf = 0; mf < 4; mf++)
#pragma unroll
                for (int nf = 0; nf < 4; nf++) {
                    mma_bf16(d[mf][nf], a[mf], bh2[nf]);
                    mma_bf16(d[mf][nf], a[mf], bl2[nf]);
                }
#pragma unroll
            for (int mf = 0; mf < 4; mf++) {
                const char* base = smc + XT_ALO + (aRow + mf * 16) * XT_ROWB + kb2;
                a[mf][0] = *(const uint32_t*)(base);
                a[mf][1] = *(const uint32_t*)(base + 8 * XT_ROWB);
                a[mf][2] = *(const uint32_t*)(base + 16);
                a[mf][3] = *(const uint32_t*)(base + 8 * XT_ROWB + 16);
            }
#pragma unroll
            for (int mf = 0; mf < 4; mf++)
#pragma unroll
                for (int nf = 0; nf < 4; nf++)
                    mma_bf16(d[mf][nf], a[mf], bh2[nf]);
        }
        __syncthreads();
    }

    const float* biasS = (const float*)(smc + XT_BIAS);
#pragma unroll
    for (int mf = 0; mf < 4; mf++)
#pragma unroll
        for (int nf = 0; nf < 4; nf++)
#pragma unroll
            for (int r8 = 0; r8 < 2; r8++) {
                int m = m0 + warpM * 64 + mf * 16 + gID + r8 * 8;
                int nl = warpN * 32 + nf * 8 + tig * 2;
                int b_ = m >> 10, s = m & 1023;
                float2 v;
                v.x = d[mf][nf][r8 * 2 + 0] + biasS[nl];
                v.y = d[mf][nf][r8 * 2 + 1] + biasS[nl + 1];
                *(float2*)&g_X[(size_t)((s << 6) + b_) * 1024 + n0 + nl] = v;
            }
}

// =====================================================================
// Phase 2: scan on tensor cores with PACKED-B split:
//   B n-slots 0..3 = h_hi batches, 4..7 = h_lo batches (n-dim was half
//   idle). Per k-step only 2 HMMA (A=Whi, A=Wlo vs the SAME B frag):
//   cols 0-3 = (Whi+Wlo)*h_hi, cols 4-7 = (Whi+Wlo)*h_lo; tail adds
//   col b + col 4+b. HMMA 24->16/warp, B LDS.128 8->4/warp.
//   h SMEM layout is byte-identical to R15 (plane offset 256 == 4*64),
//   so h0 init / staging / exchange are unchanged.
//   Red fp32 [kh(2)][col(8)][row 128 pad->132] (conflict-free STS.32).
//   Out-stores offloaded to warps 4-7 via fp32 Stg32 (bar.sync 1,256).
//   Waiter = warp 15; split S2 barrier (bar 4).
// =====================================================================
// smB byte map:
//   [0, 8192)        Hsm2 (2 parities x 4096)
//   [8192, 16640)    Red  (2 kh x 8 cols x 132 floats = 8448B)
//   [16640, 17664)   Stg  (2 parities x 512B, bf16 planes)
//   [17664, 18176)   Stg32 (128 fp32 h for out-warps)
#define SC_RED 8192
#define SC_STG 16640
#define SC_ST32 17664
#define SC_BYTES 18432

__global__ void __cluster_dims__(8, 1, 1) __launch_bounds__(512, 1)
lstm_scan(const float* __restrict__ h0, const float* __restrict__ c0,
          float* __restrict__ out, int out_size)
{
    __shared__ __align__(16) char smB[SC_BYTES];
    __shared__ __align__(16) ull mbars[2];

    const int tid = threadIdx.x;
    const int lane = tid & 31, w = tid >> 5;
    const int gID = lane >> 2, tig = lane & 3;
    unsigned rank; asm("mov.u32 %0, %%cluster_ctarank;" : "=r"(rank));
    const int b0 = (blockIdx.x >> 3) * 4;

    const int khalf = w >> 3, w7 = w & 7;
    const int mrow0 = w7 << 4;                 // warp's first row (0..112)
    const int gate  = w7 >> 1;
    const int uu0   = (w7 & 1) << 4;

    // ---- static A fragments (weights, bf16 split) into registers
    uint32_t waH[8][4], waL[8][4];
    {
        const size_t r0 = (size_t)(gate * 256 + ((int)rank << 5) + uu0 + gID) * 256;
        const size_t r1 = r0 + 8 * 256;
#pragma unroll
        for (int q = 0; q < 8; q++) {
            int kk = (khalf * 8 + q) * 16 + tig * 2;
            waH[q][0] = *(const uint32_t*)(g_Wh_hi + r0 + kk);
            waH[q][1] = *(const uint32_t*)(g_Wh_hi + r1 + kk);
            waH[q][2] = *(const uint32_t*)(g_Wh_hi + r0 + kk + 8);
            waH[q][3] = *(const uint32_t*)(g_Wh_hi + r1 + kk + 8);
            waL[q][0] = *(const uint32_t*)(g_Wh_lo + r0 + kk);
            waL[q][1] = *(const uint32_t*)(g_Wh_lo + r1 + kk);
            waL[q][2] = *(const uint32_t*)(g_Wh_lo + r0 + kk + 8);
            waL[q][3] = *(const uint32_t*)(g_Wh_lo + r1 + kk + 8);
        }
    }

    // ---- h0 -> bf16 split planes into Hsm2[parity 0] (same as R15)
    for (int e = tid; e < 1024; e += 512) {
        int b = e >> 8, k = e & 255;
        float v = h0[(size_t)(b0 + b) * 256 + k];
        __nv_bfloat16 hi = __float2bfloat16(v);
        __nv_bfloat16 lo = __float2bfloat16(v - __bfloat162float(hi));
        int rblk = k >> 5, kq = k & 31;
        int ks1 = kq >> 4, rr = kq & 15;
        int tg = (rr >> 1) & 3, bs = rr >> 3, jj = rr & 1;
        int off = rblk * 512 + b * 64 + tg * 16 + ks1 * 8 + bs * 4 + jj * 2;
        *(__nv_bfloat16*)(smB + off) = hi;
        *(__nv_bfloat16*)(smB + off + 256) = lo;
    }

    // tail roles (tid < 128): cu = lane, cb = warp
    const int cu = tid & 31, cb = (tid >> 5) & 3;
    const int ug = ((int)rank << 5) + cu;
    float c_reg = 0.0f;
    if (tid < 128) c_reg = c0[(size_t)(b0 + cb) * 256 + ug];
    int st_off;
    {
        int ks1 = cu >> 4, rr = cu & 15;
        int tg = (rr >> 1) & 3, bs = rr >> 3, jj = rr & 1;
        st_off = cb * 64 + tg * 16 + ks1 * 8 + bs * 4 + jj * 2;
    }

    // out-warp roles (128 <= tid < 256)
    const int oidx = tid - 128;
    const int ocu = oidx & 31, ocb = (oidx >> 5) & 3;
    const int oug = ((int)rank << 5) + ocu;

    unsigned smem_u32, mbar_base;
    asm("{ .reg .u64 t; cvta.to.shared.u64 t, %1; cvt.u32.u64 %0, t; }"
        : "=r"(smem_u32) : "l"(smB));
    asm("{ .reg .u64 t; cvta.to.shared.u64 t, %1; cvt.u32.u64 %0, t; }"
        : "=r"(mbar_base) : "l"(mbars));
    const unsigned mbar0 = mbar_base;
    const unsigned mbar1 = mbar_base + 8;

    const int peer = (tid < 7) ? ((tid >= (int)rank) ? tid + 1 : tid) : 0;

    if (tid == 0) {
        asm volatile("mbarrier.init.shared.b64 [%0], 1;" :: "r"(mbar0) : "memory");
        asm volatile("mbarrier.init.shared.b64 [%0], 1;" :: "r"(mbar1) : "memory");
    }
    __syncthreads();
    asm volatile("barrier.cluster.arrive.aligned;" ::: "memory");
    asm volatile("barrier.cluster.wait.aligned;" ::: "memory");

    unsigned ph0 = 0, ph1 = 0;
    float x0 = 0.f, x1 = 0.f, x2 = 0.f, x3 = 0.f;

    for (int t = 0; t < SS; t++) {
        const int p = t & 1;

        // ---- x prefetch (h-independent): issue BEFORE the wait
        if (tid < 128) {
            const float* xp = g_X + (size_t)t * 65536
                            + (size_t)(b0 + cb) * 1024 + ug;
            x0 = xp[0]; x1 = xp[256]; x2 = xp[512]; x3 = xp[768];
        }

        // ---- dedicated waiter: warp 15 polls; __syncthreads releases all
        if (t > 0) {
            if (tid >= 480) {
                const unsigned wb  = p ? mbar1 : mbar0;
                const unsigned phw = p ? ph1 : ph0;
                if (tid == 480)
                    asm volatile("mbarrier.arrive.expect_tx.shared.b64 _, [%0], %1;"
                                 :: "r"(wb), "r"(3584u) : "memory");
                asm volatile("{\n\t.reg .pred P1;\n\t"
                    "LW_%=:\n\t"
                    "mbarrier.try_wait.parity.acquire.cta.shared::cta.b64 P1, [%0], %1, 0x989680;\n\t"
                    "@P1 bra.uni LD_%=;\n\t"
                    "bra.uni LW_%=;\n\t"
                    "LD_%=:\n\t}"
                    :: "r"(wb), "r"(phw) : "memory");
            }
            if (p) ph1 ^= 1; else ph0 ^= 1;
        }
        __syncthreads();   // S1: Hsm2[p] complete

        // ---- GEMM (packed-B): 16 HMMA, 4 LDS.128 per warp
        {
            const char* hb = smB + (p << 12) + gID * 64 + tig * 16;
            float cA[4] = {0.f, 0.f, 0.f, 0.f};
            float cBv[4] = {0.f, 0.f, 0.f, 0.f};
#pragma unroll
            for (int rb = 0; rb < 4; rb++) {
                const char* blk = hb + ((khalf * 4 + rb) << 9);
                uint4 Bq = *(const uint4*)blk;
                const int q = rb * 2;
                {
                    uint32_t bf[2] = {Bq.x, Bq.y};
                    mma_bf16(cA, waH[q], bf);
                    mma_bf16(cA, waL[q], bf);
                }
                {
                    uint32_t bf[2] = {Bq.z, Bq.w};
                    mma_bf16(cBv, waH[q + 1], bf);
                    mma_bf16(cBv, waL[q + 1], bf);
                }
            }
#pragma unroll
            for (int i = 0; i < 4; i++) cA[i] += cBv[i];
            // Red[kh][col][row] fp32, col = tig*2 + {0,1}, rows gID, gID+8
            float* rf = (float*)(smB + SC_RED) + khalf * 1056;
            const int row = mrow0 + gID;
            rf[(tig * 2) * 132 + row]         = cA[0];
            rf[(tig * 2 + 1) * 132 + row]     = cA[1];
            rf[(tig * 2) * 132 + row + 8]     = cA[2];
            rf[(tig * 2 + 1) * 132 + row + 8] = cA[3];
        }

        // ---- S2 split: tail blocks until all 512 arrived; others pass
        if (tid < 128) {
            asm volatile("bar.sync 4, 512;" ::: "memory");
        } else {
            asm volatile("bar.arrive 4, 512;" ::: "memory");
        }

        if (tid < 128) {
            // ---- tail: reduce (2 kh x 2 cols), gates, c, stage, exchange
            const float* rf = (float*)(smB + SC_RED);
            float pi = 0.f, pf = 0.f, pg = 0.f, po = 0.f;
#pragma unroll
            for (int kh = 0; kh < 2; kh++) {
                const float* rk = rf + kh * 1056;
                pi += rk[cb * 132 + cu]            + rk[(cb + 4) * 132 + cu];
                pf += rk[cb * 132 + 32 + cu]       + rk[(cb + 4) * 132 + 32 + cu];
                pg += rk[cb * 132 + 64 + cu]       + rk[(cb + 4) * 132 + 64 + cu];
                po += rk[cb * 132 + 96 + cu]       + rk[(cb + 4) * 132 + 96 + cu];
            }
            pi += x0; pf += x1; pg += x2; po += x3;
            float gi = fast_sigmoid(pi);
            float gf = fast_sigmoid(pf);
            float gg = fast_tanh(pg);
            float go = fast_sigmoid(po);
            c_reg = gf * c_reg + gi * gg;
            float h = go * fast_tanh(c_reg);

            __nv_bfloat16 hhi = __float2bfloat16(h);
            __nv_bfloat16 hlo = __float2bfloat16(h - __bfloat162float(hhi));
            {
                char* sp = smB + SC_STG + (p << 9);
                *(__nv_bfloat16*)(sp + st_off) = hhi;
                *(__nv_bfloat16*)(sp + st_off + 256) = hlo;
                char* hp = smB + ((1 - p) << 12) + ((int)rank << 9);
                *(__nv_bfloat16*)(hp + st_off) = hhi;
                *(__nv_bfloat16*)(hp + st_off + 256) = hlo;
                ((float*)(smB + SC_ST32))[(cb << 5) + cu] = h;
            }
            if (t == SS - 1) {
                size_t basee = (size_t)BB * SS * HH;
                if (out_size >= (int)(basee + 2u * BB * HH)) {
                    out[basee + (size_t)(b0 + cb) * 256 + ug] = h;
                    out[basee + (size_t)BB * HH + (size_t)(b0 + cb) * 256 + ug] = c_reg;
                }
            }

            asm volatile("bar.sync 1, 256;" ::: "memory");

            if (tid < 7 && t < SS - 1) {
                asm volatile("fence.proxy.async.shared::cta;" ::: "memory");
                unsigned dstl = smem_u32 + (((unsigned)(1 - p)) << 12)
                              + ((unsigned)rank << 9);
                unsigned mbl  = p ? mbar0 : mbar1;
                unsigned srcl = smem_u32 + SC_STG + ((unsigned)p << 9);
                unsigned rdst, rmb;
                asm volatile("mapa.shared::cluster.u32 %0, %1, %2;"
                             : "=r"(rdst) : "r"(dstl), "r"(peer));
                asm volatile("mapa.shared::cluster.u32 %0, %1, %2;"
                             : "=r"(rmb) : "r"(mbl), "r"(peer));
                asm volatile(
                    "cp.async.bulk.shared::cluster.shared::cta."
                    "mbarrier::complete_tx::bytes [%0], [%1], 512, [%2];"
                    :: "r"(rdst), "r"(srcl), "r"(rmb) : "memory");
            }
        } else if (tid < 256) {
            // ---- out-warps: wait for staging, then global stores
            asm volatile("bar.sync 1, 256;" ::: "memory");
            float h = ((float*)(smB + SC_ST32))[oidx];
            float h2 = __shfl_down_sync(0xffffffffu, h, 1);
            if ((ocu & 1) == 0) {
                *(float2*)&out[((size_t)(b0 + ocb) * 1024 + t) * 256 + oug] =
                    make_float2(h, h2);
            }
        }
    }
}

// =====================================================================
extern "C" void kernel_launch(void* const* d_in, const int* in_sizes, int n_in,
                              void* d_out, int out_size)
{
    (void)in_sizes; (void)n_in;
    const float* inputs = (const float*)d_in[0];
    const float* h0     = (const float*)d_in[1];
    const float* c0     = (const float*)d_in[2];
    const float* w_ii   = (const float*)d_in[3];
    const float* w_if   = (const float*)d_in[4];
    const float* w_ig   = (const float*)d_in[5];
    const float* w_io   = (const float*)d_in[6];
    const float* b_ii   = (const float*)d_in[7];
    const float* b_if   = (const float*)d_in[8];
    const float* b_ig   = (const float*)d_in[9];
    const float* b_io   = (const float*)d_in[10];
    const float* w_hi   = (const float*)d_in[11];
    const float* w_hf   = (const float*)d_in[12];
    const float* w_hg   = (const float*)d_in[13];
    const float* w_ho   = (const float*)d_in[14];
    const float* b_hi   = (const float*)d_in[15];
    const float* b_hf   = (const float*)d_in[16];
    const float* b_hg   = (const float*)d_in[17];
    const float* b_ho   = (const float*)d_in[18];
    float* out = (float*)d_out;

    __nv_bfloat16 *ahi, *alo, *whi_p, *wlo_p, *whh, *whl;
    cudaGetSymbolAddress((void**)&ahi,   g_A_hi);
    cudaGetSymbolAddress((void**)&alo,   g_A_lo);
    cudaGetSymbolAddress((void**)&whi_p, g_W_hi);
    cudaGetSymbolAddress((void**)&wlo_p, g_W_lo);
    cudaGetSymbolAddress((void**)&whh,   g_Wh_hi);
    cudaGetSymbolAddress((void**)&whl,   g_Wh_lo);

    cvt_split<<<2048, 256>>>(inputs, ahi, alo, (BB * SS * II) / 4);
    cvt_split<<<64, 256>>>(w_ii, whi_p + 0 * 65536, wlo_p + 0 * 65536, 65536 / 4);
    cvt_split<<<64, 256>>>(w_if, whi_p + 1 * 65536, wlo_p + 1 * 65536, 65536 / 4);
    cvt_split<<<64, 256>>>(w_ig, whi_p + 2 * 65536, wlo_p + 2 * 65536, 65536 / 4);
    cvt_split<<<64, 256>>>(w_io, whi_p + 3 * 65536, wlo_p + 3 * 65536, 65536 / 4);
    cvt_split<<<64, 256>>>(w_hi, whh + 0 * 65536, whl + 0 * 65536, 65536 / 4);
    cvt_split<<<64, 256>>>(w_hf, whh + 1 * 65536, whl + 1 * 65536, 65536 / 4);
    cvt_split<<<64, 256>>>(w_hg, whh + 2 * 65536, whl + 2 * 65536, 65536 / 4);
    cvt_split<<<64, 256>>>(w_ho, whh + 3 * 65536, whl + 3 * 65536, 65536 / 4);

    lstm_xproj_tc<<<dim3(8, 512), 256>>>(
        b_ii, b_if, b_ig, b_io, b_hi, b_hf, b_hg, b_ho);

    lstm_scan<<<128, 512>>>(h0, c0, out, out_size);
}

// round 17
// speedup vs baseline: 1.5352x; 1.0027x over previous
#include <cuda_runtime.h>
#include <cuda_bf16.h>
#include <cstdint>
#include <cstddef>

typedef unsigned long long ull;

// Problem constants
#define BB 64
#define SS 1024
#define II 256
#define HH 256

// Scratch: X gate pre-activations [S][B][4*H] fp32, biases included. 256MB.
__device__ float g_X[(size_t)SS * BB * 4 * HH];
// Split-bf16 planes of A (inputs, [B*S][I]) and W (4 gates concat, [1024][256]).
__device__ __nv_bfloat16 g_A_hi[(size_t)BB * SS * II];
__device__ __nv_bfloat16 g_A_lo[(size_t)BB * SS * II];
__device__ __nv_bfloat16 g_W_hi[4 * HH * II];
__device__ __nv_bfloat16 g_W_lo[4 * HH * II];
// Split-bf16 planes of the recurrent weights (4 gates concat, [1024][256]).
__device__ __nv_bfloat16 g_Wh_hi[4 * HH * HH];
__device__ __nv_bfloat16 g_Wh_lo[4 * HH * HH];

// Accurate fast activations (ex2/rcp approx: ~2^-22 rel err, >> 1e-3 budget)
__device__ __forceinline__ float fast_sigmoid(float x) {
    float e; asm("ex2.approx.f32 %0, %1;" : "=f"(e) : "f"(-x * 1.4426950408889634f));
    float r; asm("rcp.approx.f32 %0, %1;" : "=f"(r) : "f"(1.0f + e));
    return r;
}
__device__ __forceinline__ float fast_tanh(float x) {
    x = fminf(15.0f, fmaxf(-15.0f, x));
    float e; asm("ex2.approx.f32 %0, %1;" : "=f"(e) : "f"(x * 2.8853900817779268f)); // e^{2x}
    float r; asm("rcp.approx.f32 %0, %1;" : "=f"(r) : "f"(e + 1.0f));
    return fmaf(-2.0f, r, 1.0f);
}

// ---------------- warp-level bf16 HMMA -----------------------------------
__device__ __forceinline__ void mma_bf16(float* d, const uint32_t* a,
                                         const uint32_t* b) {
    asm volatile(
        "mma.sync.aligned.m16n8k16.row.col.f32.bf16.bf16.f32 "
        "{%0,%1,%2,%3}, {%4,%5,%6,%7}, {%8,%9}, {%0,%1,%2,%3};"
        : "+f"(d[0]), "+f"(d[1]), "+f"(d[2]), "+f"(d[3])
        : "r"(a[0]), "r"(a[1]), "r"(a[2]), "r"(a[3]), "r"(b[0]), "r"(b[1]));
}

// =====================================================================
// Split-bf16 conversion:  x -> (hi, lo) with x = hi + lo + O(2^-18 x)
// =====================================================================
__global__ void cvt_split(const float* __restrict__ src,
                          __nv_bfloat16* __restrict__ hi,
                          __nv_bfloat16* __restrict__ lo, int n4)
{
    int i = blockIdx.x * blockDim.x + threadIdx.x;
    int stride = gridDim.x * blockDim.x;
    for (; i < n4; i += stride) {
        float4 v = ((const float4*)src)[i];
        float f[4] = {v.x, v.y, v.z, v.w};
        unsigned short hb[4], lb[4];
#pragma unroll
        for (int c = 0; c < 4; c++) {
            __nv_bfloat16 h = __float2bfloat16(f[c]);
            float hf = __bfloat162float(h);
            __nv_bfloat16 l = __float2bfloat16(f[c] - hf);
            hb[c] = __bfloat16_as_ushort(h);
            lb[c] = __bfloat16_as_ushort(l);
        }
        ((ushort4*)hi)[i] = make_ushort4(hb[0], hb[1], hb[2], hb[3]);
        ((ushort4*)lo)[i] = make_ushort4(lb[0], lb[1], lb[2], lb[3]);
    }
}

// =====================================================================
// Phase 1 (tensor pipe, warp HMMA): X = inputs . W^T + bias, 3-term
// bf16 split. UNCHANGED (passed, ~300us).
// =====================================================================
#define XT_ROWB 80
#define XT_TILE (128 * XT_ROWB)
#define XT_AHI 0
#define XT_ALO (1 * XT_TILE)
#define XT_BHI (2 * XT_TILE)
#define XT_BLO (3 * XT_TILE)
#define XT_BIAS (4 * XT_TILE)
#define XT_SMEM (XT_BIAS + 512)

__global__ void __launch_bounds__(256, 2) lstm_xproj_tc(
    const float* __restrict__ bii, const float* __restrict__ bif_,
    const float* __restrict__ big_, const float* __restrict__ bio,
    const float* __restrict__ bhi, const float* __restrict__ bhf,
    const float* __restrict__ bhg, const float* __restrict__ bho)
{
    __shared__ char smc[XT_SMEM];
    const int tid = threadIdx.x;
    const int lane = tid & 31, wid = tid >> 5;
    const int warpM = wid >> 2, warpN = wid & 3;
    const int gID = lane >> 2, tig = lane & 3;
    const int n0 = blockIdx.x << 7;
    const int m0 = blockIdx.y << 7;

    if (tid < 128) {
        int n = n0 + tid;
        int g = n >> 8, u = n & 255;
        const float* bi = (g == 0) ? bii : (g == 1) ? bif_ : (g == 2) ? big_ : bio;
        const float* bh = (g == 0) ? bhi : (g == 1) ? bhf : (g == 2) ? bhg : bho;
        ((float*)(smc + XT_BIAS))[tid] = bi[u] + bh[u];
    }

    float d[4][4][4];
#pragma unroll
    for (int mf = 0; mf < 4; mf++)
#pragma unroll
        for (int nf = 0; nf < 4; nf++)
#pragma unroll
            for (int c = 0; c < 4; c++) d[mf][nf][c] = 0.0f;

    const int aRow = warpM * 64 + gID;
    const int bRow = warpN * 32 + gID;

#pragma unroll 1
    for (int ch = 0; ch < 8; ch++) {
        const int k0 = ch << 5;
#pragma unroll
        for (int part = 0; part < 8; part++) {
            const int tile = part >> 1;
            int idx = part * 256 + tid;
            int r = (idx >> 2) & 127;
            int k8 = idx & 3;
            const __nv_bfloat16* src;
            if (tile == 0)      src = g_A_hi + (((size_t)(m0 + r)) << 8) + k0 + (k8 << 3);
            else if (tile == 1) src = g_A_lo + (((size_t)(m0 + r)) << 8) + k0 + (k8 << 3);
            else if (tile == 2) src = g_W_hi + (((size_t)(n0 + r)) << 8) + k0 + (k8 << 3);
            else                src = g_W_lo + (((size_t)(n0 + r)) << 8) + k0 + (k8 << 3);
            uint4 v = *(const uint4*)src;
            *(uint4*)(smc + tile * XT_TILE + r * XT_ROWB + (k8 << 4)) = v;
        }
        __syncthreads();

#pragma unroll
        for (int ks = 0; ks < 2; ks++) {
            const int kb2 = (ks * 16 + tig * 2) * 2;
            uint32_t a[4][4], bh2[4][2], bl2[4][2];
#pragma unroll
            for (int mf = 0; mf < 4; mf++) {
                const char* base = smc + XT_AHI + (aRow + mf * 16) * XT_ROWB + kb2;
                a[mf][0] = *(const uint32_t*)(base);
                a[mf][1] = *(const uint32_t*)(base + 8 * XT_ROWB);
                a[mf][2] = *(const uint32_t*)(base + 16);
                a[mf][3] = *(const uint32_t*)(base + 8 * XT_ROWB + 16);
            }
#pragma unroll
            for (int nf = 0; nf < 4; nf++) {
                const char* bh_b = smc + XT_BHI + (bRow + nf * 8) * XT_ROWB + kb2;
                bh2[nf][0] = *(const uint32_t*)(bh_b);
                bh2[nf][1] = *(const uint32_t*)(bh_b + 16);
                const char* bl_b = smc + XT_BLO + (bRow + nf * 8) * XT_ROWB + kb2;
                bl2[nf][0] = *(const uint32_t*)(bl_b);
                bl2[nf][1] = *(const uint32_t*)(bl_b + 16);
            }
#pragma unroll
            for (int mf = 0; mf < 4; mf++)
#pragma unroll
                for (int nf = 0; nf < 4; nf++) {
                    mma_bf16(d[mf][nf], a[mf], bh2[nf]);
                    mma_bf16(d[mf][nf], a[mf], bl2[nf]);
                }
#pragma unroll
            for (int mf = 0; mf < 4; mf++) {
                const char* base = smc + XT_ALO + (aRow + mf * 16) * XT_ROWB + kb2;
                a[mf][0] = *(const uint32_t*)(base);
                a[mf][1] = *(const uint32_t*)(base + 8 * XT_ROWB);
                a[mf][2] = *(const uint32_t*)(base + 16);
                a[mf][3] = *(const uint32_t*)(base + 8 * XT_ROWB + 16);
            }
#pragma unroll
            for (int mf = 0; mf < 4; mf++)
#pragma unroll
                for (int nf = 0; nf < 4; nf++)
                    mma_bf16(d[mf][nf], a[mf], bh2[nf]);
        }
        __syncthreads();
    }

    const float* biasS = (const float*)(smc + XT_BIAS);
#pragma unroll
    for (int mf = 0; mf < 4; mf++)
#pragma unroll
        for (int nf = 0; nf < 4; nf++)
#pragma unroll
            for (int r8 = 0; r8 < 2; r8++) {
                int m = m0 + warpM * 64 + mf * 16 + gID + r8 * 8;
                int nl = warpN * 32 + nf * 8 + tig * 2;
                int b_ = m >> 10, s = m & 1023;
                float2 v;
                v.x = d[mf][nf][r8 * 2 + 0] + biasS[nl];
                v.y = d[mf][nf][r8 * 2 + 1] + biasS[nl + 1];
                *(float2*)&g_X[(size_t)((s << 6) + b_) * 1024 + n0 + nl] = v;
            }
}

// =====================================================================
// Phase 2: scan on tensor cores, packed-B split (R16 base) with:
//  - SPIN-WAIT: waiter warp polls mbarrier.test_wait (no suspend) so
//    partial tx arrivals don't trigger sleep/wake thrash.
//  - Staging buffer removed: peer copies source directly from
//    Hsm[1-p][rank] (tail already writes that block locally).
// =====================================================================
// smB byte map:
//   [0, 8192)        Hsm2 (2 parities x 4096)
//   [8192, 16640)    Red  (2 kh x 8 cols x 132 floats = 8448B)
//   [16640, 17152)   Stg32 (128 fp32 h for out-warps)
#define SC_RED 8192
#define SC_ST32 16640
#define SC_BYTES 17408

__global__ void __cluster_dims__(8, 1, 1) __launch_bounds__(512, 1)
lstm_scan(const float* __restrict__ h0, const float* __restrict__ c0,
          float* __restrict__ out, int out_size)
{
    __shared__ __align__(16) char smB[SC_BYTES];
    __shared__ __align__(16) ull mbars[2];

    const int tid = threadIdx.x;
    const int lane = tid & 31, w = tid >> 5;
    const int gID = lane >> 2, tig = lane & 3;
    unsigned rank; asm("mov.u32 %0, %%cluster_ctarank;" : "=r"(rank));
    const int b0 = (blockIdx.x >> 3) * 4;

    const int khalf = w >> 3, w7 = w & 7;
    const int mrow0 = w7 << 4;
    const int gate  = w7 >> 1;
    const int uu0   = (w7 & 1) << 4;

    // ---- static A fragments (weights, bf16 split) into registers
    uint32_t waH[8][4], waL[8][4];
    {
        const size_t r0 = (size_t)(gate * 256 + ((int)rank << 5) + uu0 + gID) * 256;
        const size_t r1 = r0 + 8 * 256;
#pragma unroll
        for (int q = 0; q < 8; q++) {
            int kk = (khalf * 8 + q) * 16 + tig * 2;
            waH[q][0] = *(const uint32_t*)(g_Wh_hi + r0 + kk);
            waH[q][1] = *(const uint32_t*)(g_Wh_hi + r1 + kk);
            waH[q][2] = *(const uint32_t*)(g_Wh_hi + r0 + kk + 8);
            waH[q][3] = *(const uint32_t*)(g_Wh_hi + r1 + kk + 8);
            waL[q][0] = *(const uint32_t*)(g_Wh_lo + r0 + kk);
            waL[q][1] = *(const uint32_t*)(g_Wh_lo + r1 + kk);
            waL[q][2] = *(const uint32_t*)(g_Wh_lo + r0 + kk + 8);
            waL[q][3] = *(const uint32_t*)(g_Wh_lo + r1 + kk + 8);
        }
    }

    // ---- h0 -> bf16 split planes into Hsm2[parity 0]
    for (int e = tid; e < 1024; e += 512) {
        int b = e >> 8, k = e & 255;
        float v = h0[(size_t)(b0 + b) * 256 + k];
        __nv_bfloat16 hi = __float2bfloat16(v);
        __nv_bfloat16 lo = __float2bfloat16(v - __bfloat162float(hi));
        int rblk = k >> 5, kq = k & 31;
        int ks1 = kq >> 4, rr = kq & 15;
        int tg = (rr >> 1) & 3, bs = rr >> 3, jj = rr & 1;
        int off = rblk * 512 + b * 64 + tg * 16 + ks1 * 8 + bs * 4 + jj * 2;
        *(__nv_bfloat16*)(smB + off) = hi;
        *(__nv_bfloat16*)(smB + off + 256) = lo;
    }

    // tail roles (tid < 128): cu = lane, cb = warp
    const int cu = tid & 31, cb = (tid >> 5) & 3;
    const int ug = ((int)rank << 5) + cu;
    float c_reg = 0.0f;
    if (tid < 128) c_reg = c0[(size_t)(b0 + cb) * 256 + ug];
    int st_off;
    {
        int ks1 = cu >> 4, rr = cu & 15;
        int tg = (rr >> 1) & 3, bs = rr >> 3, jj = rr & 1;
        st_off = cb * 64 + tg * 16 + ks1 * 8 + bs * 4 + jj * 2;
    }

    // out-warp roles (128 <= tid < 256)
    const int oidx = tid - 128;
    const int ocu = oidx & 31, ocb = (oidx >> 5) & 3;
    const int oug = ((int)rank << 5) + ocu;

    unsigned smem_u32, mbar_base;
    asm("{ .reg .u64 t; cvta.to.shared.u64 t, %1; cvt.u32.u64 %0, t; }"
        : "=r"(smem_u32) : "l"(smB));
    asm("{ .reg .u64 t; cvta.to.shared.u64 t, %1; cvt.u32.u64 %0, t; }"
        : "=r"(mbar_base) : "l"(mbars));
    const unsigned mbar0 = mbar_base;
    const unsigned mbar1 = mbar_base + 8;

    const int peer = (tid < 7) ? ((tid >= (int)rank) ? tid + 1 : tid) : 0;

    if (tid == 0) {
        asm volatile("mbarrier.init.shared.b64 [%0], 1;" :: "r"(mbar0) : "memory");
        asm volatile("mbarrier.init.shared.b64 [%0], 1;" :: "r"(mbar1) : "memory");
    }
    __syncthreads();
    asm volatile("barrier.cluster.arrive.aligned;" ::: "memory");
    asm volatile("barrier.cluster.wait.aligned;" ::: "memory");

    unsigned ph0 = 0, ph1 = 0;
    float x0 = 0.f, x1 = 0.f, x2 = 0.f, x3 = 0.f;

    for (int t = 0; t < SS; t++) {
        const int p = t & 1;

        // ---- x prefetch (h-independent): issue BEFORE the wait
        if (tid < 128) {
            const float* xp = g_X + (size_t)t * 65536
                            + (size_t)(b0 + cb) * 1024 + ug;
            x0 = xp[0]; x1 = xp[256]; x2 = xp[512]; x3 = xp[768];
        }

        // ---- dedicated waiter (warp 15), SPIN on test_wait (no suspend)
        if (t > 0) {
            if (tid >= 480) {
                const unsigned wb  = p ? mbar1 : mbar0;
                const unsigned phw = p ? ph1 : ph0;
                if (tid == 480)
                    asm volatile("mbarrier.arrive.expect_tx.shared.b64 _, [%0], %1;"
                                 :: "r"(wb), "r"(3584u) : "memory");
                asm volatile("{\n\t.reg .pred P1;\n\t"
                    "LW_%=:\n\t"
                    "mbarrier.test_wait.parity.acquire.cta.shared::cta.b64 P1, [%0], %1;\n\t"
                    "@P1 bra.uni LD_%=;\n\t"
                    "bra.uni LW_%=;\n\t"
                    "LD_%=:\n\t}"
                    :: "r"(wb), "r"(phw) : "memory");
            }
            if (p) ph1 ^= 1; else ph0 ^= 1;
        }
        __syncthreads();   // S1: Hsm2[p] complete

        // ---- GEMM (packed-B): 16 HMMA, 4 LDS.128 per warp
        {
            const char* hb = smB + (p << 12) + gID * 64 + tig * 16;
            float cA[4] = {0.f, 0.f, 0.f, 0.f};
            float cBv[4] = {0.f, 0.f, 0.f, 0.f};
#pragma unroll
            for (int rb = 0; rb < 4; rb++) {
                const char* blk = hb + ((khalf * 4 + rb) << 9);
                uint4 Bq = *(const uint4*)blk;
                const int q = rb * 2;
                {
                    uint32_t bf[2] = {Bq.x, Bq.y};
                    mma_bf16(cA, waH[q], bf);
                    mma_bf16(cA, waL[q], bf);
                }
                {
                    uint32_t bf[2] = {Bq.z, Bq.w};
                    mma_bf16(cBv, waH[q + 1], bf);
                    mma_bf16(cBv, waL[q + 1], bf);
                }
            }
#pragma unroll
            for (int i = 0; i < 4; i++) cA[i] += cBv[i];
            float* rf = (float*)(smB + SC_RED) + khalf * 1056;
            const int row = mrow0 + gID;
            rf[(tig * 2) * 132 + row]         = cA[0];
            rf[(tig * 2 + 1) * 132 + row]     = cA[1];
            rf[(tig * 2) * 132 + row + 8]     = cA[2];
            rf[(tig * 2 + 1) * 132 + row + 8] = cA[3];
        }

        // ---- S2 split: tail blocks until all 512 arrived; others pass
        if (tid < 128) {
            asm volatile("bar.sync 4, 512;" ::: "memory");
        } else {
            asm volatile("bar.arrive 4, 512;" ::: "memory");
        }

        if (tid < 128) {
            // ---- tail: reduce (2 kh x 2 cols), gates, c, write, exchange
            const float* rf = (float*)(smB + SC_RED);
            float pi = 0.f, pf = 0.f, pg = 0.f, po = 0.f;
#pragma unroll
            for (int kh = 0; kh < 2; kh++) {
                const float* rk = rf + kh * 1056;
                pi += rk[cb * 132 + cu]            + rk[(cb + 4) * 132 + cu];
                pf += rk[cb * 132 + 32 + cu]       + rk[(cb + 4) * 132 + 32 + cu];
                pg += rk[cb * 132 + 64 + cu]       + rk[(cb + 4) * 132 + 64 + cu];
                po += rk[cb * 132 + 96 + cu]       + rk[(cb + 4) * 132 + 96 + cu];
            }
            pi += x0; pf += x1; pg += x2; po += x3;
            float gi = fast_sigmoid(pi);
            float gf = fast_sigmoid(pf);
            float gg = fast_tanh(pg);
            float go = fast_sigmoid(po);
            c_reg = gf * c_reg + gi * gg;
            float h = go * fast_tanh(c_reg);

            __nv_bfloat16 hhi = __float2bfloat16(h);
            __nv_bfloat16 hlo = __float2bfloat16(h - __bfloat162float(hhi));
            {
                // own block straight into next Hsm (also the copy SOURCE)
                char* hp = smB + ((1 - p) << 12) + ((int)rank << 9);
                *(__nv_bfloat16*)(hp + st_off) = hhi;
                *(__nv_bfloat16*)(hp + st_off + 256) = hlo;
                ((float*)(smB + SC_ST32))[(cb << 5) + cu] = h;
            }
            if (t == SS - 1) {
                size_t basee = (size_t)BB * SS * HH;
                if (out_size >= (int)(basee + 2u * BB * HH)) {
                    out[basee + (size_t)(b0 + cb) * 256 + ug] = h;
                    out[basee + (size_t)BB * HH + (size_t)(b0 + cb) * 256 + ug] = c_reg;
                }
            }

            asm volatile("bar.sync 1, 256;" ::: "memory");

            if (tid < 7 && t < SS - 1) {
                asm volatile("fence.proxy.async.shared::cta;" ::: "memory");
                unsigned dstl = smem_u32 + (((unsigned)(1 - p)) << 12)
                              + ((unsigned)rank << 9);
                unsigned mbl  = p ? mbar0 : mbar1;
                unsigned srcl = dstl;   // source = own Hsm[1-p][rank] block
                unsigned rdst, rmb;
                asm volatile("mapa.shared::cluster.u32 %0, %1, %2;"
                             : "=r"(rdst) : "r"(dstl), "r"(peer));
                asm volatile("mapa.shared::cluster.u32 %0, %1, %2;"
                             : "=r"(rmb) : "r"(mbl), "r"(peer));
                asm volatile(
                    "cp.async.bulk.shared::cluster.shared::cta."
                    "mbarrier::complete_tx::bytes [%0], [%1], 512, [%2];"
                    :: "r"(rdst), "r"(srcl), "r"(rmb) : "memory");
            }
        } else if (tid < 256) {
            // ---- out-warps: wait for staging, then global stores
            asm volatile("bar.sync 1, 256;" ::: "memory");
            float h = ((float*)(smB + SC_ST32))[oidx];
            float h2 = __shfl_down_sync(0xffffffffu, h, 1);
            if ((ocu & 1) == 0) {
                *(float2*)&out[((size_t)(b0 + ocb) * 1024 + t) * 256 + oug] =
                    make_float2(h, h2);
            }
        }
    }
}

// =====================================================================
extern "C" void kernel_launch(void* const* d_in, const int* in_sizes, int n_in,
                              void* d_out, int out_size)
{
    (void)in_sizes; (void)n_in;
    const float* inputs = (const float*)d_in[0];
    const float* h0     = (const float*)d_in[1];
    const float* c0     = (const float*)d_in[2];
    const float* w_ii   = (const float*)d_in[3];
    const float* w_if   = (const float*)d_in[4];
    const float* w_ig   = (const float*)d_in[5];
    const float* w_io   = (const float*)d_in[6];
    const float* b_ii   = (const float*)d_in[7];
    const float* b_if   = (const float*)d_in[8];
    const float* b_ig   = (const float*)d_in[9];
    const float* b_io   = (const float*)d_in[10];
    const float* w_hi   = (const float*)d_in[11];
    const float* w_hf   = (const float*)d_in[12];
    const float* w_hg   = (const float*)d_in[13];
    const float* w_ho   = (const float*)d_in[14];
    const float* b_hi   = (const float*)d_in[15];
    const float* b_hf   = (const float*)d_in[16];
    const float* b_hg   = (const float*)d_in[17];
    const float* b_ho   = (const float*)d_in[18];
    float* out = (float*)d_out;

    __nv_bfloat16 *ahi, *alo, *whi_p, *wlo_p, *whh, *whl;
    cudaGetSymbolAddress((void**)&ahi,   g_A_hi);
    cudaGetSymbolAddress((void**)&alo,   g_A_lo);
    cudaGetSymbolAddress((void**)&whi_p, g_W_hi);
    cudaGetSymbolAddress((void**)&wlo_p, g_W_lo);
    cudaGetSymbolAddress((void**)&whh,   g_Wh_hi);
    cudaGetSymbolAddress((void**)&whl,   g_Wh_lo);

    cvt_split<<<2048, 256>>>(inputs, ahi, alo, (BB * SS * II) / 4);
    cvt_split<<<64, 256>>>(w_ii, whi_p + 0 * 65536, wlo_p + 0 * 65536, 65536 / 4);
    cvt_split<<<64, 256>>>(w_if, whi_p + 1 * 65536, wlo_p + 1 * 65536, 65536 / 4);
    cvt_split<<<64, 256>>>(w_ig, whi_p + 2 * 65536, wlo_p + 2 * 65536, 65536 / 4);
    cvt_split<<<64, 256>>>(w_io, whi_p + 3 * 65536, wlo_p + 3 * 65536, 65536 / 4);
    cvt_split<<<64, 256>>>(w_hi, whh + 0 * 65536, whl + 0 * 65536, 65536 / 4);
    cvt_split<<<64, 256>>>(w_hf, whh + 1 * 65536, whl + 1 * 65536, 65536 / 4);
    cvt_split<<<64, 256>>>(w_hg, whh + 2 * 65536, whl + 2 * 65536, 65536 / 4);
    cvt_split<<<64, 256>>>(w_ho, whh + 3 * 65536, whl + 3 * 65536, 65536 / 4);

    lstm_xproj_tc<<<dim3(8, 512), 256>>>(
        b_ii, b_if, b_ig, b_io, b_hi, b_hf, b_hg, b_ho);

    lstm_scan<<<128, 512>>>(h0, c0, out, out_size);
}